// round 3
// baseline (speedup 1.0000x reference)
#include <cuda_runtime.h>
#include <math.h>

// Problem constants (fixed shapes from reference setup_inputs)
#define CB      1024      // n_embd
#define NH      16        // heads
#define DH      64        // head dim
#define TT      4096      // seq len
#define BBATCH  2         // batch
#define WINDOW  256
#define STRIDE  128
#define NGLOB   16

// Scratch (device globals: allocation-free per harness rules)
__device__ float g_q [BBATCH*NH*TT*DH];   // [b,h,t,d]
__device__ float g_k [BBATCH*NH*TT*DH];   // [b,h,t,d]
__device__ float g_kT[BBATCH*NH*DH*TT];   // [b,h,d,t]
__device__ float g_v [BBATCH*NH*TT*DH];   // [b,h,t,d]
__device__ float g_y [BBATCH*TT*CB];      // [b,t,c] attention output

// ---------------------------------------------------------------------------
// Tiled SGEMM: 128x128 block tile, 16-deep K tile, 8x8 per-thread microtile,
// 256 threads. MODE 0: A = g_y (proj), plain epilogue to C with bias.
//               MODE 1: A = param (x), scatter epilogue into q/k/kT/v.
// M,N,K all multiples of tile sizes here, so no bounds checks.
// ---------------------------------------------------------------------------
template <int MODE>
__global__ void __launch_bounds__(256, 2)
sgemm(const float* __restrict__ Ain, const float* __restrict__ Bw,
      const float* __restrict__ bias, float* __restrict__ C,
      int M, int N, int K)
{
    const float* A = (MODE == 0) ? (const float*)g_y : Ain;

    __shared__ float As[16][132];   // [k][m], padded
    __shared__ float Bs[16][128];   // [k][n]

    const int tid  = threadIdx.x;
    const int bm   = blockIdx.y * 128;
    const int bn   = blockIdx.x * 128;

    const int arow = tid >> 2;          // 0..63  (A tile row, +64 for second)
    const int acol = (tid & 3) << 2;    // 0,4,8,12
    const int brow = tid >> 5;          // 0..7   (B tile row, +8 for second)
    const int bcol = (tid & 31) << 2;   // 0..124
    const int tx   = tid & 15;
    const int ty   = tid >> 4;

    float acc[8][8];
    #pragma unroll
    for (int a = 0; a < 8; a++)
        #pragma unroll
        for (int bq = 0; bq < 8; bq++) acc[a][bq] = 0.f;

    const float* Aptr = A  + (size_t)(bm + arow) * K + acol;
    const float* Bptr = Bw + (size_t)brow * N + bn + bcol;

    for (int k0 = 0; k0 < K; k0 += 16) {
        #pragma unroll
        for (int r = 0; r < 2; r++) {
            float4 a4 = *(const float4*)(Aptr + (size_t)r * 64 * K + k0);
            As[acol + 0][arow + r * 64] = a4.x;
            As[acol + 1][arow + r * 64] = a4.y;
            As[acol + 2][arow + r * 64] = a4.z;
            As[acol + 3][arow + r * 64] = a4.w;
            float4 b4 = *(const float4*)(Bptr + (size_t)(k0 + r * 8) * N);
            *(float4*)&Bs[brow + r * 8][bcol] = b4;
        }
        __syncthreads();

        #pragma unroll
        for (int kk = 0; kk < 16; kk++) {
            float af[8], bf[8];
            #pragma unroll
            for (int u = 0; u < 8; u++) af[u] = As[kk][ty * 8 + u];
            #pragma unroll
            for (int u = 0; u < 8; u++) bf[u] = Bs[kk][tx * 8 + u];
            #pragma unroll
            for (int um = 0; um < 8; um++)
                #pragma unroll
                for (int un = 0; un < 8; un++)
                    acc[um][un] += af[um] * bf[un];
        }
        __syncthreads();
    }

    // bias for this thread's 8 columns
    float bv[8];
    #pragma unroll
    for (int un = 0; un < 8; un++) bv[un] = bias[bn + tx * 8 + un];

    if (MODE == 0) {
        // plain epilogue -> C
        #pragma unroll
        for (int um = 0; um < 8; um++) {
            const int mrow = bm + ty * 8 + um;
            float* crow = C + (size_t)mrow * N + bn + tx * 8;
            float4 o0, o1;
            o0.x = acc[um][0] + bv[0]; o0.y = acc[um][1] + bv[1];
            o0.z = acc[um][2] + bv[2]; o0.w = acc[um][3] + bv[3];
            o1.x = acc[um][4] + bv[4]; o1.y = acc[um][5] + bv[5];
            o1.z = acc[um][6] + bv[6]; o1.w = acc[um][7] + bv[7];
            *(float4*)(crow + 0) = o0;
            *(float4*)(crow + 4) = o1;
        }
    } else {
        // scatter epilogue into q / k / kT / v
        // Section (q/k/v) is uniform per block: bn is 128-aligned, sections 1024-aligned.
        const int sec = bn >> 10;                 // 0=q, 1=k, 2=v
        const int f0  = (bn & 1023) + tx * 8;     // feature offset within section
        const int hh  = f0 >> 6;                  // head
        const int d0  = f0 & 63;                  // head-dim base (8-aligned, stays in head)
        #pragma unroll
        for (int um = 0; um < 8; um++) {
            const int mrow = bm + ty * 8 + um;
            const int bidx = mrow >> 12;          // /4096
            const int t    = mrow & (TT - 1);
            const int bh   = bidx * NH + hh;
            float vals[8];
            #pragma unroll
            for (int un = 0; un < 8; un++) vals[un] = acc[um][un] + bv[un];
            const size_t base = ((size_t)bh * TT + t) * DH + d0;
            float4 o0, o1;
            o0.x = vals[0]; o0.y = vals[1]; o0.z = vals[2]; o0.w = vals[3];
            o1.x = vals[4]; o1.y = vals[5]; o1.z = vals[6]; o1.w = vals[7];
            if (sec == 0) {
                *(float4*)&g_q[base] = o0; *(float4*)&g_q[base + 4] = o1;
            } else if (sec == 2) {
                *(float4*)&g_v[base] = o0; *(float4*)&g_v[base + 4] = o1;
            } else {
                *(float4*)&g_k[base] = o0; *(float4*)&g_k[base + 4] = o1;
                #pragma unroll
                for (int un = 0; un < 8; un++)
                    g_kT[((size_t)bh * DH + d0 + un) * TT + t] = vals[un];
            }
        }
    }
}

// ---------------------------------------------------------------------------
// Sparse causal attention. One warp per query (4 warps / block).
// Disjoint key sets per query i (lo = max(0, i-255)):
//   A: window  j in [lo, i]                          (contiguous; lanes=keys vs kT)
//   B: stride  j = i - 128*s, s>=2, j >= 16          (serial; lane=d + shfl reduce)
//   C: global  j in [0, min(16, lo))                 (serial; lane=d + shfl reduce)
// Online softmax state per warp; output g_y in [b,t,h,d] (== [b,t,c]).
// ---------------------------------------------------------------------------
__global__ void __launch_bounds__(128)
attn()
{
    const int lane = threadIdx.x & 31;
    const int warp = threadIdx.x >> 5;
    const int i    = blockIdx.x * 4 + warp;
    const int h    = blockIdx.y;
    const int b    = blockIdx.z;
    const int bh   = b * NH + h;

    __shared__ float sq[4][64];
    __shared__ float sp[4][32];

    const float* qrow = g_q + ((size_t)bh * TT + i) * DH;
    sq[warp][lane]      = qrow[lane];
    sq[warp][lane + 32] = qrow[lane + 32];
    __syncwarp();
    const float q0r = sq[warp][lane];
    const float q1r = sq[warp][lane + 32];

    const float scale = 0.125f;   // 1/sqrt(64)
    float m = -INFINITY, l = 0.f, acc0 = 0.f, acc1 = 0.f;

    const float* kTb = g_kT + (size_t)bh * DH * TT;
    const float* kb  = g_k  + (size_t)bh * TT * DH;
    const float* vb  = g_v  + (size_t)bh * TT * DH;

    const int lo = max(0, i - (WINDOW - 1));

    // ---- Phase A: window, 32-key chunks aligned to 32 (shared across warps) ----
    for (int c = (lo & ~31); c <= i; c += 32) {
        const int j  = c + lane;
        const int jc = min(j, i);            // clamp keeps loads in-bounds
        float s0 = 0.f, s1 = 0.f, s2 = 0.f, s3 = 0.f;
        #pragma unroll
        for (int d = 0; d < 64; d += 4) {
            s0 += sq[warp][d + 0] * kTb[(d + 0) * TT + jc];
            s1 += sq[warp][d + 1] * kTb[(d + 1) * TT + jc];
            s2 += sq[warp][d + 2] * kTb[(d + 2) * TT + jc];
            s3 += sq[warp][d + 3] * kTb[(d + 3) * TT + jc];
        }
        float s = ((s0 + s1) + (s2 + s3)) * scale;
        if (j < lo || j > i) s = -INFINITY;

        float cm = s;
        #pragma unroll
        for (int off = 16; off; off >>= 1)
            cm = fmaxf(cm, __shfl_xor_sync(0xffffffffu, cm, off));
        const float mnew = fmaxf(m, cm);
        const float p    = __expf(s - mnew);   // exp(-inf - finite) = 0 for masked
        float csum = p;
        #pragma unroll
        for (int off = 16; off; off >>= 1)
            csum += __shfl_xor_sync(0xffffffffu, csum, off);
        const float alpha = __expf(m - mnew);  // first chunk: exp(-inf)=0
        m = mnew;
        l = l * alpha + csum;
        acc0 *= alpha; acc1 *= alpha;

        sp[warp][lane] = p;
        __syncwarp();
        #pragma unroll 8
        for (int kk = 0; kk < 32; kk++) {
            const int jj   = min(c + kk, i);
            const float pv = sp[warp][kk];     // 0 for masked lanes
            const float* vr = vb + (size_t)jj * DH;
            acc0 += pv * vr[lane];
            acc1 += pv * vr[lane + 32];
        }
        __syncwarp();
    }

    // ---- Phases B + C: serial keys, lane=d, warp-sum reduce ----
    auto process_key = [&](int j) {
        const float* kr = kb + (size_t)j * DH;
        float part = q0r * kr[lane] + q1r * kr[lane + 32];
        #pragma unroll
        for (int off = 16; off; off >>= 1)
            part += __shfl_xor_sync(0xffffffffu, part, off);
        const float s     = part * scale;
        const float mnew  = fmaxf(m, s);
        const float alpha = __expf(m - mnew);
        const float p     = __expf(s - mnew);
        m = mnew;
        l = l * alpha + p;
        const float* vr = vb + (size_t)j * DH;
        acc0 = acc0 * alpha + p * vr[lane];
        acc1 = acc1 * alpha + p * vr[lane + 32];
    };

    for (int j = i - 2 * STRIDE; j >= NGLOB; j -= STRIDE) process_key(j);  // B
    const int cmax = min(NGLOB, lo);
    for (int j = 0; j < cmax; j++) process_key(j);                          // C

    const float inv = 1.f / l;
    float* yr = g_y + ((size_t)b * TT + i) * CB + h * DH;
    yr[lane]      = acc0 * inv;
    yr[lane + 32] = acc1 * inv;
}

// ---------------------------------------------------------------------------
extern "C" void kernel_launch(void* const* d_in, const int* in_sizes, int n_in,
                              void* d_out, int out_size)
{
    (void)in_sizes; (void)n_in; (void)out_size;
    const float* x      = (const float*)d_in[0];
    const float* w_qkv  = (const float*)d_in[1];
    const float* b_qkv  = (const float*)d_in[2];
    const float* w_proj = (const float*)d_in[3];
    const float* b_proj = (const float*)d_in[4];
    float* out = (float*)d_out;

    const int M = BBATCH * TT;   // 8192

    // 1) QKV GEMM with scatter epilogue -> g_q / g_k / g_kT / g_v
    sgemm<1><<<dim3((3 * CB) / 128, M / 128), 256>>>(
        x, w_qkv, b_qkv, nullptr, M, 3 * CB, CB);

    // 2) Sparse causal attention -> g_y
    attn<<<dim3(TT / 4, NH, BBATCH), 128>>>();

    // 3) Output projection GEMM (A = g_y internally) -> d_out
    sgemm<0><<<dim3(CB / 128, M / 128), 256>>>(
        nullptr, w_proj, b_proj, out, M, CB, CB);
}

// round 5
// speedup vs baseline: 1.5140x; 1.5140x over previous
#include <cuda_runtime.h>
#include <cuda_bf16.h>
#include <math.h>
#include <stdint.h>

// Problem constants (fixed shapes from reference setup_inputs)
#define CB      1024      // n_embd
#define NH      16        // heads
#define DH      64        // head dim
#define TT      4096      // seq len
#define BBATCH  2         // batch
#define WINDOW  256
#define STRIDE  128
#define NGLOB   16

#define MTOT    (BBATCH*TT)          // 8192
#define N_QKV   (3*CB)               // 3072

// ---------------------------------------------------------------------------
// Scratch (device globals: allocation-free per harness rules)
// ---------------------------------------------------------------------------
__device__ float g_q [BBATCH*NH*TT*DH];   // [b,h,t,d]
__device__ float g_k [BBATCH*NH*TT*DH];   // [b,h,t,d]
__device__ float g_kT[BBATCH*NH*DH*TT];   // [b,h,d,t]
__device__ float g_v [BBATCH*NH*TT*DH];   // [b,h,t,d]
__device__ float g_y [BBATCH*TT*CB];      // [b,t,c] attention output

__device__ __align__(128) __nv_bfloat16 g_xhi[MTOT*CB];     // bf16-hi of x
__device__ __align__(128) __nv_bfloat16 g_xlo[MTOT*CB];     // bf16-lo of x
__device__ __align__(128) __nv_bfloat16 g_yhi[MTOT*CB];
__device__ __align__(128) __nv_bfloat16 g_ylo[MTOT*CB];
__device__ __align__(128) __nv_bfloat16 g_wqT_hi[N_QKV*CB]; // w_qkv^T [N,K]
__device__ __align__(128) __nv_bfloat16 g_wqT_lo[N_QKV*CB];
__device__ __align__(128) __nv_bfloat16 g_wpT_hi[CB*CB];    // w_proj^T [N,K]
__device__ __align__(128) __nv_bfloat16 g_wpT_lo[CB*CB];

// ---------------------------------------------------------------------------
// PTX helpers (all sm_80+ portable: cp.async / ldmatrix / mma.sync)
// ---------------------------------------------------------------------------
__device__ __forceinline__ uint32_t su32(const void* p) {
    return (uint32_t)__cvta_generic_to_shared(p);
}
__device__ __forceinline__ void cpa16(uint32_t s, const void* g) {
    asm volatile("cp.async.cg.shared.global [%0], [%1], 16;\n" :: "r"(s), "l"(g));
}
__device__ __forceinline__ void cpa_commit() {
    asm volatile("cp.async.commit_group;\n" ::);
}
template <int NW> __device__ __forceinline__ void cpa_wait() {
    asm volatile("cp.async.wait_group %0;\n" :: "n"(NW));
}
__device__ __forceinline__ void ldm_x4(uint32_t* r, uint32_t addr) {
    asm volatile("ldmatrix.sync.aligned.m8n8.x4.shared.b16 {%0,%1,%2,%3}, [%4];"
                 : "=r"(r[0]), "=r"(r[1]), "=r"(r[2]), "=r"(r[3]) : "r"(addr));
}
__device__ __forceinline__ void ldm_x2(uint32_t* r, uint32_t addr) {
    asm volatile("ldmatrix.sync.aligned.m8n8.x2.shared.b16 {%0,%1}, [%2];"
                 : "=r"(r[0]), "=r"(r[1]) : "r"(addr));
}
__device__ __forceinline__ void mma16816(float* c, const uint32_t* a, const uint32_t* b) {
    asm volatile("mma.sync.aligned.m16n8k16.row.col.f32.bf16.bf16.f32 "
                 "{%0,%1,%2,%3}, {%4,%5,%6,%7}, {%8,%9}, {%0,%1,%2,%3};"
                 : "+f"(c[0]), "+f"(c[1]), "+f"(c[2]), "+f"(c[3])
                 : "r"(a[0]), "r"(a[1]), "r"(a[2]), "r"(a[3]), "r"(b[0]), "r"(b[1]));
}
__device__ __forceinline__ __nv_bfloat16 bf_hi(float x) { return __float2bfloat16_rn(x); }

// ---------------------------------------------------------------------------
// Preprocessing: bf16 hi/lo splits and transpose-splits
// ---------------------------------------------------------------------------
__global__ void split_x(const float4* __restrict__ src) {
    int i = blockIdx.x * blockDim.x + threadIdx.x;   // MTOT*CB/4 threads
    float4 v = src[i];
    __nv_bfloat162 h01, h23, l01, l23;
    h01.x = bf_hi(v.x); l01.x = bf_hi(v.x - __bfloat162float(h01.x));
    h01.y = bf_hi(v.y); l01.y = bf_hi(v.y - __bfloat162float(h01.y));
    h23.x = bf_hi(v.z); l23.x = bf_hi(v.z - __bfloat162float(h23.x));
    h23.y = bf_hi(v.w); l23.y = bf_hi(v.w - __bfloat162float(h23.y));
    ((__nv_bfloat162*)g_xhi)[2 * i]     = h01;
    ((__nv_bfloat162*)g_xhi)[2 * i + 1] = h23;
    ((__nv_bfloat162*)g_xlo)[2 * i]     = l01;
    ((__nv_bfloat162*)g_xlo)[2 * i + 1] = l23;
}
__global__ void split_y() {
    int i = blockIdx.x * blockDim.x + threadIdx.x;
    float4 v = ((const float4*)g_y)[i];
    __nv_bfloat162 h01, h23, l01, l23;
    h01.x = bf_hi(v.x); l01.x = bf_hi(v.x - __bfloat162float(h01.x));
    h01.y = bf_hi(v.y); l01.y = bf_hi(v.y - __bfloat162float(h01.y));
    h23.x = bf_hi(v.z); l23.x = bf_hi(v.z - __bfloat162float(h23.x));
    h23.y = bf_hi(v.w); l23.y = bf_hi(v.w - __bfloat162float(h23.y));
    ((__nv_bfloat162*)g_yhi)[2 * i]     = h01;
    ((__nv_bfloat162*)g_yhi)[2 * i + 1] = h23;
    ((__nv_bfloat162*)g_ylo)[2 * i]     = l01;
    ((__nv_bfloat162*)g_ylo)[2 * i + 1] = l23;
}
// W [K,N] row-major -> WT_hi/WT_lo [N,K] bf16
template <int SEL>
__global__ void transpose_split(const float* __restrict__ W, int K, int N) {
    __nv_bfloat16* Thi = (SEL == 0) ? g_wqT_hi : g_wpT_hi;
    __nv_bfloat16* Tlo = (SEL == 0) ? g_wqT_lo : g_wpT_lo;
    __shared__ float t[32][33];
    const int n0 = blockIdx.x * 32, k0 = blockIdx.y * 32;
    const int tx = threadIdx.x, ty = threadIdx.y;
    #pragma unroll
    for (int r = ty; r < 32; r += 8)
        t[r][tx] = W[(size_t)(k0 + r) * N + n0 + tx];
    __syncthreads();
    #pragma unroll
    for (int r = ty; r < 32; r += 8) {
        float v = t[tx][r];                       // W[k0+tx][n0+r]
        __nv_bfloat16 h = bf_hi(v);
        __nv_bfloat16 l = bf_hi(v - __bfloat162float(h));
        size_t o = (size_t)(n0 + r) * K + k0 + tx;
        Thi[o] = h;
        Tlo[o] = l;
    }
}

// ---------------------------------------------------------------------------
// bf16x3 tensor-core GEMM via mma.sync.m16n8k16 (HMMA path, target-portable).
// D[M,N] = A[M,K] * B[N,K]^T ; A,B each split into bf16 hi+lo; 3 MMA combos.
// Tile 128x128x32, 3-stage cp.async pipeline (32KB/stage), 8 warps (2x4),
// each warp 64x32 (4x4 m16n8 tiles). 16B-chunk swizzle: c ^= (row>>1)&3.
// MODE 1: scatter epilogue -> q/k/kT/v.  MODE 0: plain epilogue -> C.
// ---------------------------------------------------------------------------
#define ST_BYTES  32768                 // per stage: Ahi|Alo|Bhi|Blo, 8KB each
#define TG_SMEM   (3*ST_BYTES)

template <int MODE>
__global__ void __launch_bounds__(256, 1)
tgemm(const float* __restrict__ bias, float* __restrict__ C, int N, int K)
{
    extern __shared__ __align__(128) unsigned char smbuf[];
    const uint32_t sbase = su32(smbuf);
    const int tid = threadIdx.x;
    const int bm = blockIdx.y * 128;
    const int bn = blockIdx.x * 128;

    const __nv_bfloat16* __restrict__ Ahi = (MODE == 1) ? g_xhi : g_yhi;
    const __nv_bfloat16* __restrict__ Alo = (MODE == 1) ? g_xlo : g_ylo;
    const __nv_bfloat16* __restrict__ Bhi = (MODE == 1) ? g_wqT_hi : g_wpT_hi;
    const __nv_bfloat16* __restrict__ Blo = (MODE == 1) ? g_wqT_lo : g_wpT_lo;

    const int NK = K / 32;   // 32

    // stage loader: per thread 2 chunks per array (16B each), 8 cp.async total
    const int ldrow = tid >> 1;            // 0..127
    const int ldc0  = (tid & 1) * 2;       // 0 or 2
    auto load_stage = [&](int stage, int k0) {
        const uint32_t sb = sbase + (uint32_t)stage * ST_BYTES;
        #pragma unroll
        for (int cc = 0; cc < 2; cc++) {
            const int c = ldc0 + cc;
            const uint32_t so = (uint32_t)(ldrow * 64 + ((c ^ ((ldrow >> 1) & 3)) << 4));
            const size_t ga = (size_t)(bm + ldrow) * K + k0 + c * 8;
            const size_t gb = (size_t)(bn + ldrow) * K + k0 + c * 8;
            cpa16(sb + so,               Ahi + ga);
            cpa16(sb + 8192 + so,        Alo + ga);
            cpa16(sb + 16384 + so,       Bhi + gb);
            cpa16(sb + 24576 + so,       Blo + gb);
        }
        cpa_commit();
    };

    load_stage(0, 0);
    load_stage(1, 32);

    const int lane = tid & 31, w = tid >> 5;
    const int wm = w >> 2, wn = w & 3;
    // ldmatrix address components
    const int a_r = lane & 15, a_c = lane >> 4;        // A: 16 rows, 2 chunk-cols
    const int b_r = lane & 7,  b_c = (lane >> 3) & 1;  // B: 8 rows, 2 chunk-cols

    float acc[4][4][4];
    #pragma unroll
    for (int mt = 0; mt < 4; mt++)
        #pragma unroll
        for (int nt = 0; nt < 4; nt++)
            #pragma unroll
            for (int q = 0; q < 4; q++) acc[mt][nt][q] = 0.f;

    for (int ks = 0; ks < NK; ks++) {
        if (ks == NK - 1) cpa_wait<0>(); else cpa_wait<1>();
        __syncthreads();
        if (ks + 2 < NK) load_stage((ks + 2) % 3, (ks + 2) * 32);

        const uint32_t sb = sbase + (uint32_t)(ks % 3) * ST_BYTES;
        #pragma unroll
        for (int t = 0; t < 2; t++) {
            uint32_t ah[4][4], al[4][4], bh[4][2], bl[4][2];
            #pragma unroll
            for (int mt = 0; mt < 4; mt++) {
                const int r = wm * 64 + mt * 16 + a_r;
                const int c = t * 2 + a_c;
                const uint32_t so = (uint32_t)(r * 64 + ((c ^ ((r >> 1) & 3)) << 4));
                ldm_x4(ah[mt], sb + so);
                ldm_x4(al[mt], sb + 8192 + so);
            }
            #pragma unroll
            for (int nt = 0; nt < 4; nt++) {
                const int r = wn * 32 + nt * 8 + b_r;
                const int c = t * 2 + b_c;
                const uint32_t so = (uint32_t)(r * 64 + ((c ^ ((r >> 1) & 3)) << 4));
                ldm_x2(bh[nt], sb + 16384 + so);
                ldm_x2(bl[nt], sb + 24576 + so);
            }
            #pragma unroll
            for (int mt = 0; mt < 4; mt++)
                #pragma unroll
                for (int nt = 0; nt < 4; nt++) {
                    mma16816(acc[mt][nt], ah[mt], bh[nt]);
                    mma16816(acc[mt][nt], ah[mt], bl[nt]);
                    mma16816(acc[mt][nt], al[mt], bh[nt]);
                }
        }
        __syncthreads();
    }

    // ---------------- epilogue ----------------
    const int colq = (lane & 3) * 2;       // col pair within n8 tile
    const int rowq = lane >> 2;            // row within m16 tile (upper half)
    #pragma unroll
    for (int nt = 0; nt < 4; nt++) {
        const int cg = bn + wn * 32 + nt * 8 + colq;   // global col
        const float b0 = bias[cg], b1 = bias[cg + 1];
        #pragma unroll
        for (int mt = 0; mt < 4; mt++) {
            const int r0 = bm + wm * 64 + mt * 16 + rowq;
            const int r1 = r0 + 8;
            float v00 = acc[mt][nt][0] + b0, v01 = acc[mt][nt][1] + b1;
            float v10 = acc[mt][nt][2] + b0, v11 = acc[mt][nt][3] + b1;
            if (MODE == 0) {
                float2 p0 = make_float2(v00, v01);
                float2 p1 = make_float2(v10, v11);
                *(float2*)(C + (size_t)r0 * N + cg) = p0;
                *(float2*)(C + (size_t)r1 * N + cg) = p1;
            } else {
                const int sec = cg >> 10;            // 0=q,1=k,2=v
                const int f  = cg & 1023;
                const int hh = f >> 6, d0 = f & 63;  // d0 even
                float* dst = (sec == 0) ? g_q : ((sec == 1) ? g_k : g_v);
                #pragma unroll
                for (int rr = 0; rr < 2; rr++) {
                    const int mrow = rr ? r1 : r0;
                    const float va = rr ? v10 : v00;
                    const float vb = rr ? v11 : v01;
                    const int bidx = mrow >> 12;
                    const int ttk  = mrow & (TT - 1);
                    const int bh2  = bidx * NH + hh;
                    const size_t base = ((size_t)bh2 * TT + ttk) * DH + d0;
                    *(float2*)(dst + base) = make_float2(va, vb);
                    if (sec == 1) {
                        g_kT[((size_t)bh2 * DH + d0)     * TT + ttk] = va;
                        g_kT[((size_t)bh2 * DH + d0 + 1) * TT + ttk] = vb;
                    }
                }
            }
        }
    }
}

// ---------------------------------------------------------------------------
// Sparse causal attention (unchanged). One warp per query.
// ---------------------------------------------------------------------------
__global__ void __launch_bounds__(128)
attn()
{
    const int lane = threadIdx.x & 31;
    const int warp = threadIdx.x >> 5;
    const int i    = blockIdx.x * 4 + warp;
    const int h    = blockIdx.y;
    const int b    = blockIdx.z;
    const int bh   = b * NH + h;

    __shared__ float sq[4][64];
    __shared__ float sp[4][32];

    const float* qrow = g_q + ((size_t)bh * TT + i) * DH;
    sq[warp][lane]      = qrow[lane];
    sq[warp][lane + 32] = qrow[lane + 32];
    __syncwarp();
    const float q0r = sq[warp][lane];
    const float q1r = sq[warp][lane + 32];

    const float scale = 0.125f;
    float m = -INFINITY, l = 0.f, acc0 = 0.f, acc1 = 0.f;

    const float* kTb = g_kT + (size_t)bh * DH * TT;
    const float* kb  = g_k  + (size_t)bh * TT * DH;
    const float* vb  = g_v  + (size_t)bh * TT * DH;

    const int lo = max(0, i - (WINDOW - 1));

    for (int c = (lo & ~31); c <= i; c += 32) {
        const int j  = c + lane;
        const int jc = min(j, i);
        float s0 = 0.f, s1 = 0.f, s2 = 0.f, s3 = 0.f;
        #pragma unroll
        for (int d = 0; d < 64; d += 4) {
            s0 += sq[warp][d + 0] * kTb[(d + 0) * TT + jc];
            s1 += sq[warp][d + 1] * kTb[(d + 1) * TT + jc];
            s2 += sq[warp][d + 2] * kTb[(d + 2) * TT + jc];
            s3 += sq[warp][d + 3] * kTb[(d + 3) * TT + jc];
        }
        float s = ((s0 + s1) + (s2 + s3)) * scale;
        if (j < lo || j > i) s = -INFINITY;

        float cm = s;
        #pragma unroll
        for (int off = 16; off; off >>= 1)
            cm = fmaxf(cm, __shfl_xor_sync(0xffffffffu, cm, off));
        const float mnew = fmaxf(m, cm);
        const float p    = __expf(s - mnew);
        float csum = p;
        #pragma unroll
        for (int off = 16; off; off >>= 1)
            csum += __shfl_xor_sync(0xffffffffu, csum, off);
        const float alpha = __expf(m - mnew);
        m = mnew;
        l = l * alpha + csum;
        acc0 *= alpha; acc1 *= alpha;

        sp[warp][lane] = p;
        __syncwarp();
        #pragma unroll 8
        for (int kk = 0; kk < 32; kk++) {
            const int jj   = min(c + kk, i);
            const float pv = sp[warp][kk];
            const float* vr = vb + (size_t)jj * DH;
            acc0 += pv * vr[lane];
            acc1 += pv * vr[lane + 32];
        }
        __syncwarp();
    }

    auto process_key = [&](int j) {
        const float* kr = kb + (size_t)j * DH;
        float part = q0r * kr[lane] + q1r * kr[lane + 32];
        #pragma unroll
        for (int off = 16; off; off >>= 1)
            part += __shfl_xor_sync(0xffffffffu, part, off);
        const float s     = part * scale;
        const float mnew  = fmaxf(m, s);
        const float alpha = __expf(m - mnew);
        const float p     = __expf(s - mnew);
        m = mnew;
        l = l * alpha + p;
        const float* vr = vb + (size_t)j * DH;
        acc0 = acc0 * alpha + p * vr[lane];
        acc1 = acc1 * alpha + p * vr[lane + 32];
    };

    for (int j = i - 2 * STRIDE; j >= NGLOB; j -= STRIDE) process_key(j);
    const int cmax = min(NGLOB, lo);
    for (int j = 0; j < cmax; j++) process_key(j);

    const float inv = 1.f / l;
    float* yr = g_y + ((size_t)b * TT + i) * CB + h * DH;
    yr[lane]      = acc0 * inv;
    yr[lane + 32] = acc1 * inv;
}

// ---------------------------------------------------------------------------
extern "C" void kernel_launch(void* const* d_in, const int* in_sizes, int n_in,
                              void* d_out, int out_size)
{
    (void)in_sizes; (void)n_in; (void)out_size;
    const float* x      = (const float*)d_in[0];
    const float* w_qkv  = (const float*)d_in[1];
    const float* b_qkv  = (const float*)d_in[2];
    const float* w_proj = (const float*)d_in[3];
    const float* b_proj = (const float*)d_in[4];
    float* out = (float*)d_out;

    cudaFuncSetAttribute(tgemm<1>, cudaFuncAttributeMaxDynamicSharedMemorySize, TG_SMEM);
    cudaFuncSetAttribute(tgemm<0>, cudaFuncAttributeMaxDynamicSharedMemorySize, TG_SMEM);

    // 0) bf16 hi/lo splits of activations + transposed weight splits
    split_x<<<(MTOT * CB / 4) / 256, 256>>>((const float4*)x);
    transpose_split<0><<<dim3(N_QKV / 32, CB / 32), dim3(32, 8)>>>(w_qkv, CB, N_QKV);
    transpose_split<1><<<dim3(CB / 32, CB / 32), dim3(32, 8)>>>(w_proj, CB, CB);

    // 1) QKV GEMM (bf16x3 tensor) with scatter epilogue -> g_q/g_k/g_kT/g_v
    tgemm<1><<<dim3(N_QKV / 128, MTOT / 128), 256, TG_SMEM>>>(b_qkv, nullptr, N_QKV, CB);

    // 2) Sparse causal attention -> g_y
    attn<<<dim3(TT / 4, NH, BBATCH), 128>>>();

    // 3) split y, then output projection GEMM -> d_out
    split_y<<<(MTOT * CB / 4) / 256, 256>>>();
    tgemm<0><<<dim3(CB / 128, MTOT / 128), 256, TG_SMEM>>>(b_proj, out, CB, CB);
}

// round 6
// speedup vs baseline: 1.6966x; 1.1206x over previous
#include <cuda_runtime.h>
#include <cuda_bf16.h>
#include <math.h>
#include <stdint.h>

// Problem constants (fixed shapes from reference setup_inputs)
#define CB      1024      // n_embd
#define NH      16        // heads
#define DH      64        // head dim
#define TT      4096      // seq len
#define BBATCH  2         // batch
#define WINDOW  256
#define STRIDE  128
#define NGLOB   16

#define MTOT    (BBATCH*TT)          // 8192
#define N_QKV   (3*CB)               // 3072

// ---------------------------------------------------------------------------
// Scratch (device globals: allocation-free per harness rules)
// ---------------------------------------------------------------------------
__device__ float g_q [BBATCH*NH*TT*DH];   // [b,h,t,d]
__device__ float g_k [BBATCH*NH*TT*DH];   // [b,h,t,d]
__device__ float g_kT[BBATCH*NH*DH*TT];   // [b,h,d,t]
__device__ float g_v [BBATCH*NH*TT*DH];   // [b,h,t,d]
__device__ float g_y [BBATCH*TT*CB];      // [b,t,c] attention output

__device__ __align__(128) __nv_bfloat16 g_xhi[MTOT*CB];     // bf16-hi of x
__device__ __align__(128) __nv_bfloat16 g_xlo[MTOT*CB];     // bf16-lo of x
__device__ __align__(128) __nv_bfloat16 g_yhi[MTOT*CB];
__device__ __align__(128) __nv_bfloat16 g_ylo[MTOT*CB];
__device__ __align__(128) __nv_bfloat16 g_wqT_hi[N_QKV*CB]; // w_qkv^T [N,K]
__device__ __align__(128) __nv_bfloat16 g_wqT_lo[N_QKV*CB];
__device__ __align__(128) __nv_bfloat16 g_wpT_hi[CB*CB];    // w_proj^T [N,K]
__device__ __align__(128) __nv_bfloat16 g_wpT_lo[CB*CB];

// ---------------------------------------------------------------------------
// PTX helpers (all sm_80+ portable: cp.async / ldmatrix / mma.sync)
// ---------------------------------------------------------------------------
__device__ __forceinline__ uint32_t su32(const void* p) {
    return (uint32_t)__cvta_generic_to_shared(p);
}
__device__ __forceinline__ void cpa16(uint32_t s, const void* g) {
    asm volatile("cp.async.cg.shared.global [%0], [%1], 16;\n" :: "r"(s), "l"(g));
}
__device__ __forceinline__ void cpa_commit() {
    asm volatile("cp.async.commit_group;\n" ::);
}
template <int NW> __device__ __forceinline__ void cpa_wait() {
    asm volatile("cp.async.wait_group %0;\n" :: "n"(NW));
}
__device__ __forceinline__ void ldm_x4(uint32_t* r, uint32_t addr) {
    asm volatile("ldmatrix.sync.aligned.m8n8.x4.shared.b16 {%0,%1,%2,%3}, [%4];"
                 : "=r"(r[0]), "=r"(r[1]), "=r"(r[2]), "=r"(r[3]) : "r"(addr));
}
__device__ __forceinline__ void ldm_x2(uint32_t* r, uint32_t addr) {
    asm volatile("ldmatrix.sync.aligned.m8n8.x2.shared.b16 {%0,%1}, [%2];"
                 : "=r"(r[0]), "=r"(r[1]) : "r"(addr));
}
__device__ __forceinline__ void mma16816(float* c, const uint32_t* a, const uint32_t* b) {
    asm volatile("mma.sync.aligned.m16n8k16.row.col.f32.bf16.bf16.f32 "
                 "{%0,%1,%2,%3}, {%4,%5,%6,%7}, {%8,%9}, {%0,%1,%2,%3};"
                 : "+f"(c[0]), "+f"(c[1]), "+f"(c[2]), "+f"(c[3])
                 : "r"(a[0]), "r"(a[1]), "r"(a[2]), "r"(a[3]), "r"(b[0]), "r"(b[1]));
}
__device__ __forceinline__ __nv_bfloat16 bf_hi(float x) { return __float2bfloat16_rn(x); }

// ---------------------------------------------------------------------------
// Preprocessing: bf16 hi/lo splits and transpose-splits
// ---------------------------------------------------------------------------
__global__ void split_x(const float4* __restrict__ src) {
    int i = blockIdx.x * blockDim.x + threadIdx.x;   // MTOT*CB/4 threads
    float4 v = src[i];
    __nv_bfloat162 h01, h23, l01, l23;
    h01.x = bf_hi(v.x); l01.x = bf_hi(v.x - __bfloat162float(h01.x));
    h01.y = bf_hi(v.y); l01.y = bf_hi(v.y - __bfloat162float(h01.y));
    h23.x = bf_hi(v.z); l23.x = bf_hi(v.z - __bfloat162float(h23.x));
    h23.y = bf_hi(v.w); l23.y = bf_hi(v.w - __bfloat162float(h23.y));
    ((__nv_bfloat162*)g_xhi)[2 * i]     = h01;
    ((__nv_bfloat162*)g_xhi)[2 * i + 1] = h23;
    ((__nv_bfloat162*)g_xlo)[2 * i]     = l01;
    ((__nv_bfloat162*)g_xlo)[2 * i + 1] = l23;
}
__global__ void split_y() {
    int i = blockIdx.x * blockDim.x + threadIdx.x;
    float4 v = ((const float4*)g_y)[i];
    __nv_bfloat162 h01, h23, l01, l23;
    h01.x = bf_hi(v.x); l01.x = bf_hi(v.x - __bfloat162float(h01.x));
    h01.y = bf_hi(v.y); l01.y = bf_hi(v.y - __bfloat162float(h01.y));
    h23.x = bf_hi(v.z); l23.x = bf_hi(v.z - __bfloat162float(h23.x));
    h23.y = bf_hi(v.w); l23.y = bf_hi(v.w - __bfloat162float(h23.y));
    ((__nv_bfloat162*)g_yhi)[2 * i]     = h01;
    ((__nv_bfloat162*)g_yhi)[2 * i + 1] = h23;
    ((__nv_bfloat162*)g_ylo)[2 * i]     = l01;
    ((__nv_bfloat162*)g_ylo)[2 * i + 1] = l23;
}
// W [K,N] row-major -> WT_hi/WT_lo [N,K] bf16
template <int SEL>
__global__ void transpose_split(const float* __restrict__ W, int K, int N) {
    __nv_bfloat16* Thi = (SEL == 0) ? g_wqT_hi : g_wpT_hi;
    __nv_bfloat16* Tlo = (SEL == 0) ? g_wqT_lo : g_wpT_lo;
    __shared__ float t[32][33];
    const int n0 = blockIdx.x * 32, k0 = blockIdx.y * 32;
    const int tx = threadIdx.x, ty = threadIdx.y;
    #pragma unroll
    for (int r = ty; r < 32; r += 8)
        t[r][tx] = W[(size_t)(k0 + r) * N + n0 + tx];
    __syncthreads();
    #pragma unroll
    for (int r = ty; r < 32; r += 8) {
        float v = t[tx][r];                       // W[k0+tx][n0+r]
        __nv_bfloat16 h = bf_hi(v);
        __nv_bfloat16 l = bf_hi(v - __bfloat162float(h));
        size_t o = (size_t)(n0 + r) * K + k0 + tx;
        Thi[o] = h;
        Tlo[o] = l;
    }
}

// ---------------------------------------------------------------------------
// bf16x3 tensor-core GEMM via mma.sync.m16n8k16 (unchanged from R5 pass).
// ---------------------------------------------------------------------------
#define ST_BYTES  32768                 // per stage: Ahi|Alo|Bhi|Blo, 8KB each
#define TG_SMEM   (3*ST_BYTES)

template <int MODE>
__global__ void __launch_bounds__(256, 1)
tgemm(const float* __restrict__ bias, float* __restrict__ C, int N, int K)
{
    extern __shared__ __align__(128) unsigned char smbuf[];
    const uint32_t sbase = su32(smbuf);
    const int tid = threadIdx.x;
    const int bm = blockIdx.y * 128;
    const int bn = blockIdx.x * 128;

    const __nv_bfloat16* __restrict__ Ahi = (MODE == 1) ? g_xhi : g_yhi;
    const __nv_bfloat16* __restrict__ Alo = (MODE == 1) ? g_xlo : g_ylo;
    const __nv_bfloat16* __restrict__ Bhi = (MODE == 1) ? g_wqT_hi : g_wpT_hi;
    const __nv_bfloat16* __restrict__ Blo = (MODE == 1) ? g_wqT_lo : g_wpT_lo;

    const int NK = K / 32;   // 32

    const int ldrow = tid >> 1;
    const int ldc0  = (tid & 1) * 2;
    auto load_stage = [&](int stage, int k0) {
        const uint32_t sb = sbase + (uint32_t)stage * ST_BYTES;
        #pragma unroll
        for (int cc = 0; cc < 2; cc++) {
            const int c = ldc0 + cc;
            const uint32_t so = (uint32_t)(ldrow * 64 + ((c ^ ((ldrow >> 1) & 3)) << 4));
            const size_t ga = (size_t)(bm + ldrow) * K + k0 + c * 8;
            const size_t gb = (size_t)(bn + ldrow) * K + k0 + c * 8;
            cpa16(sb + so,               Ahi + ga);
            cpa16(sb + 8192 + so,        Alo + ga);
            cpa16(sb + 16384 + so,       Bhi + gb);
            cpa16(sb + 24576 + so,       Blo + gb);
        }
        cpa_commit();
    };

    load_stage(0, 0);
    load_stage(1, 32);

    const int lane = tid & 31, w = tid >> 5;
    const int wm = w >> 2, wn = w & 3;
    const int a_r = lane & 15, a_c = lane >> 4;
    const int b_r = lane & 7,  b_c = (lane >> 3) & 1;

    float acc[4][4][4];
    #pragma unroll
    for (int mt = 0; mt < 4; mt++)
        #pragma unroll
        for (int nt = 0; nt < 4; nt++)
            #pragma unroll
            for (int q = 0; q < 4; q++) acc[mt][nt][q] = 0.f;

    for (int ks = 0; ks < NK; ks++) {
        if (ks == NK - 1) cpa_wait<0>(); else cpa_wait<1>();
        __syncthreads();
        if (ks + 2 < NK) load_stage((ks + 2) % 3, (ks + 2) * 32);

        const uint32_t sb = sbase + (uint32_t)(ks % 3) * ST_BYTES;
        #pragma unroll
        for (int t = 0; t < 2; t++) {
            uint32_t ah[4][4], al[4][4], bh[4][2], bl[4][2];
            #pragma unroll
            for (int mt = 0; mt < 4; mt++) {
                const int r = wm * 64 + mt * 16 + a_r;
                const int c = t * 2 + a_c;
                const uint32_t so = (uint32_t)(r * 64 + ((c ^ ((r >> 1) & 3)) << 4));
                ldm_x4(ah[mt], sb + so);
                ldm_x4(al[mt], sb + 8192 + so);
            }
            #pragma unroll
            for (int nt = 0; nt < 4; nt++) {
                const int r = wn * 32 + nt * 8 + b_r;
                const int c = t * 2 + b_c;
                const uint32_t so = (uint32_t)(r * 64 + ((c ^ ((r >> 1) & 3)) << 4));
                ldm_x2(bh[nt], sb + 16384 + so);
                ldm_x2(bl[nt], sb + 24576 + so);
            }
            #pragma unroll
            for (int mt = 0; mt < 4; mt++)
                #pragma unroll
                for (int nt = 0; nt < 4; nt++) {
                    mma16816(acc[mt][nt], ah[mt], bh[nt]);
                    mma16816(acc[mt][nt], ah[mt], bl[nt]);
                    mma16816(acc[mt][nt], al[mt], bh[nt]);
                }
        }
        __syncthreads();
    }

    const int colq = (lane & 3) * 2;
    const int rowq = lane >> 2;
    #pragma unroll
    for (int nt = 0; nt < 4; nt++) {
        const int cg = bn + wn * 32 + nt * 8 + colq;
        const float b0 = bias[cg], b1 = bias[cg + 1];
        #pragma unroll
        for (int mt = 0; mt < 4; mt++) {
            const int r0 = bm + wm * 64 + mt * 16 + rowq;
            const int r1 = r0 + 8;
            float v00 = acc[mt][nt][0] + b0, v01 = acc[mt][nt][1] + b1;
            float v10 = acc[mt][nt][2] + b0, v11 = acc[mt][nt][3] + b1;
            if (MODE == 0) {
                *(float2*)(C + (size_t)r0 * N + cg) = make_float2(v00, v01);
                *(float2*)(C + (size_t)r1 * N + cg) = make_float2(v10, v11);
            } else {
                const int sec = cg >> 10;
                const int f  = cg & 1023;
                const int hh = f >> 6, d0 = f & 63;
                float* dst = (sec == 0) ? g_q : ((sec == 1) ? g_k : g_v);
                #pragma unroll
                for (int rr = 0; rr < 2; rr++) {
                    const int mrow = rr ? r1 : r0;
                    const float va = rr ? v10 : v00;
                    const float vb = rr ? v11 : v01;
                    const int bidx = mrow >> 12;
                    const int ttk  = mrow & (TT - 1);
                    const int bh2  = bidx * NH + hh;
                    const size_t base = ((size_t)bh2 * TT + ttk) * DH + d0;
                    *(float2*)(dst + base) = make_float2(va, vb);
                    if (sec == 1) {
                        g_kT[((size_t)bh2 * DH + d0)     * TT + ttk] = va;
                        g_kT[((size_t)bh2 * DH + d0 + 1) * TT + ttk] = vb;
                    }
                }
            }
        }
    }
}

// ---------------------------------------------------------------------------
// Tiled sparse attention v2 (flash-style, fp32 FFMA).
// CTA = 64 queries x (b,h). 8 warps. Q tile in smem; K^T and V streamed in
// 64-key double-buffered cp.async blocks. Register-tiled scores (warp grid
// 2x4, micro 4x4) -> smem; per-warp online softmax (warp w owns rows w*8..);
// register-tiled PV (micro 4qx4d). Far stride keys (j<=i-384) serial.
// ---------------------------------------------------------------------------
// smem float offsets
#define A_QS   0                        // 64 x 65
#define A_SS   (A_QS + 64*65)           // 64 x 67
#define A_M    (A_SS + 64*67)           // 64
#define A_L    (A_M + 64)               // 64
#define A_AL   (A_L + 64)               // 64
#define A_KS   (A_AL + 64)              // 2 x 64x64   (K^T: [d][k])
#define A_VS   (A_KS + 2*64*64)         // 2 x 64x64   (V:   [k][d])
#define A_TOT  (A_VS + 2*64*64)
#define ATTN_SMEM (A_TOT * 4)           // 100,096 bytes

__global__ void __launch_bounds__(256, 2)
attn2()
{
    extern __shared__ __align__(16) float sm[];
    const int tid  = threadIdx.x;
    const int lane = tid & 31;
    const int w    = tid >> 5;
    const int q0   = blockIdx.x * 64;
    const int h    = blockIdx.y;
    const int b    = blockIdx.z;
    const int bh   = b * NH + h;
    const uint32_t sb32 = su32(sm);

    // ---- load Q tile (pitch 65), init m/l ----
    {
        const float* qsrc = g_q + ((size_t)bh * TT + q0) * DH;
        for (int e = tid; e < 64 * 64; e += 256) {
            const int r = e >> 6, d = e & 63;
            sm[A_QS + r * 65 + d] = qsrc[(size_t)r * DH + d];
        }
        if (tid < 64) { sm[A_M + tid] = -INFINITY; sm[A_L + tid] = 0.f; }
    }

    // ---- key-block schedule ----
    const int kstart = (q0 > 256) ? (q0 - 256) : 0;
    const int extra  = (kstart > 0) ? 1 : 0;       // separate global block
    const int nb     = (q0 + 64 - kstart) / 64 + extra;
    auto kb_of = [&](int bi) -> int {
        return (extra && bi == 0) ? 0 : kstart + (bi - extra) * 64;
    };

    // cp.async loader for one 64-key block into buffer `buf`
    auto load_kv = [&](int buf, int kb) {
        const float* ksrc = g_kT + (size_t)bh * DH * TT + kb;      // [d][t]
        const float* vsrc = g_v  + ((size_t)bh * TT + kb) * DH;    // [t][d]
        #pragma unroll
        for (int qq = 0; qq < 8; qq++) {
            const int id = tid + qq * 256;          // 0..2047
            if (id < 1024) {
                const int d = id >> 4, cx = id & 15;
                cpa16(sb32 + (A_KS + buf * 4096 + d * 64 + cx * 4) * 4,
                      ksrc + (size_t)d * TT + cx * 4);
            } else {
                const int r = (id - 1024) >> 4, cx = id & 15;
                cpa16(sb32 + (A_VS + buf * 4096 + r * 64 + cx * 4) * 4,
                      vsrc + (size_t)r * DH + cx * 4);
            }
        }
        cpa_commit();
    };

    load_kv(0, kb_of(0));

    // lane mappings
    const int wq = w >> 2, wk = w & 3;          // scores warp grid 2x4
    const int lq = lane >> 2, lk = lane & 3;    // scores lane grid 8x4
    const int lq2 = lane >> 4, ld = lane & 15;  // PV lane grid 2x16
    const int r0 = w * 8;                       // softmax/PV row ownership

    float acc[4][4];
    #pragma unroll
    for (int a = 0; a < 4; a++)
        #pragma unroll
        for (int d = 0; d < 4; d++) acc[a][d] = 0.f;

    __syncthreads();   // Q tile + m/l ready

    for (int bi = 0; bi < nb; bi++) {
        const int kb  = kb_of(bi);
        const int buf = bi & 1;
        const bool gonly = (extra && bi == 0);

        if (bi + 1 < nb) { load_kv(buf ^ 1, kb_of(bi + 1)); cpa_wait<1>(); }
        else             { cpa_wait<0>(); }
        __syncthreads();

        // ---- scores: S[64q][64k] register-tiled ----
        {
            float sacc[4][4];
            #pragma unroll
            for (int a = 0; a < 4; a++)
                #pragma unroll
                for (int c = 0; c < 4; c++) sacc[a][c] = 0.f;
            const int qb = wq * 32 + lq * 4;
            const int kbk = wk * 16 + lk * 4;
            #pragma unroll 4
            for (int d = 0; d < 64; d++) {
                const float4 bb = *(const float4*)&sm[A_KS + buf * 4096 + d * 64 + kbk];
                float av[4];
                #pragma unroll
                for (int a = 0; a < 4; a++) av[a] = sm[A_QS + (qb + a) * 65 + d];
                #pragma unroll
                for (int a = 0; a < 4; a++) {
                    sacc[a][0] += av[a] * bb.x;
                    sacc[a][1] += av[a] * bb.y;
                    sacc[a][2] += av[a] * bb.z;
                    sacc[a][3] += av[a] * bb.w;
                }
            }
            #pragma unroll
            for (int a = 0; a < 4; a++) {
                const int i = q0 + qb + a;
                #pragma unroll
                for (int c = 0; c < 4; c++) {
                    const int j = kb + kbk + c;
                    const int dij = i - j;
                    bool ok;
                    if (gonly) ok = (j < NGLOB);
                    else ok = (dij >= 0) &&
                              (dij < WINDOW || (dij & (STRIDE - 1)) == 0 || j < NGLOB);
                    sm[A_SS + (qb + a) * 67 + kbk + c] = ok ? sacc[a][c] * 0.125f : -INFINITY;
                }
            }
        }
        __syncthreads();

        // ---- online softmax: warp w owns rows r0..r0+7 ----
        #pragma unroll
        for (int t = 0; t < 8; t++) {
            const int row = r0 + t;
            float s0 = sm[A_SS + row * 67 + lane];
            float s1 = sm[A_SS + row * 67 + lane + 32];
            float rmax = fmaxf(s0, s1);
            #pragma unroll
            for (int off = 16; off; off >>= 1)
                rmax = fmaxf(rmax, __shfl_xor_sync(0xffffffffu, rmax, off));
            const float mold = sm[A_M + row];
            const float mnew = fmaxf(mold, rmax);
            const float p0 = __expf(s0 - mnew), p1 = __expf(s1 - mnew);
            sm[A_SS + row * 67 + lane]      = p0;
            sm[A_SS + row * 67 + lane + 32] = p1;
            float rsum = p0 + p1;
            #pragma unroll
            for (int off = 16; off; off >>= 1)
                rsum += __shfl_xor_sync(0xffffffffu, rsum, off);
            const float alpha = __expf(mold - mnew);
            if (lane == 0) {
                sm[A_AL + row] = alpha;
                sm[A_M + row]  = mnew;
                sm[A_L + row]  = sm[A_L + row] * alpha + rsum;
            }
        }
        __syncthreads();

        // ---- PV accumulate: warp w rows r0..r0+7, micro 4q x 4d ----
        {
            const int qb = r0 + lq2 * 4;
            #pragma unroll
            for (int a = 0; a < 4; a++) {
                const float alpha = sm[A_AL + qb + a];
                acc[a][0] *= alpha; acc[a][1] *= alpha;
                acc[a][2] *= alpha; acc[a][3] *= alpha;
            }
            #pragma unroll 4
            for (int kk = 0; kk < 64; kk++) {
                const float4 vv = *(const float4*)&sm[A_VS + buf * 4096 + kk * 64 + ld * 4];
                #pragma unroll
                for (int a = 0; a < 4; a++) {
                    const float p = sm[A_SS + (qb + a) * 67 + kk];
                    acc[a][0] += p * vv.x;
                    acc[a][1] += p * vv.y;
                    acc[a][2] += p * vv.z;
                    acc[a][3] += p * vv.w;
                }
            }
        }
        __syncthreads();
    }

    // ---- far stride keys: j = i-384, i-512, ... >= 16 (serial, warp-owned rows)
    #pragma unroll 1
    for (int t = 0; t < 8; t++) {
        const int row = r0 + t;
        const int i = q0 + row;
        int j = i - 3 * STRIDE;
        if (j >= NGLOB) {
            float m_r = sm[A_M + row];
            float l_r = sm[A_L + row];
            const float qa = sm[A_QS + row * 65 + lane];
            const float qbv = sm[A_QS + row * 65 + lane + 32];
            const bool own = ((t >> 2) == lq2);
            const int qi = t & 3;
            for (; j >= NGLOB; j -= STRIDE) {
                const float* kr = g_k + ((size_t)bh * TT + j) * DH;
                float part = qa * kr[lane] + qbv * kr[lane + 32];
                #pragma unroll
                for (int off = 16; off; off >>= 1)
                    part += __shfl_xor_sync(0xffffffffu, part, off);
                const float s = part * 0.125f;
                const float mnew = fmaxf(m_r, s);
                const float alpha = __expf(m_r - mnew);
                const float p = __expf(s - mnew);
                l_r = l_r * alpha + p;
                m_r = mnew;
                if (own) {
                    const float4 vj = *(const float4*)(g_v + ((size_t)bh * TT + j) * DH + ld * 4);
                    acc[qi][0] = acc[qi][0] * alpha + p * vj.x;
                    acc[qi][1] = acc[qi][1] * alpha + p * vj.y;
                    acc[qi][2] = acc[qi][2] * alpha + p * vj.z;
                    acc[qi][3] = acc[qi][3] * alpha + p * vj.w;
                }
            }
            if (lane == 0) { sm[A_M + row] = m_r; sm[A_L + row] = l_r; }
            __syncwarp();
        }
    }

    // ---- normalize + write y ----
    #pragma unroll
    for (int a = 0; a < 4; a++) {
        const int row = r0 + lq2 * 4 + a;
        const float inv = 1.f / sm[A_L + row];
        float4 o;
        o.x = acc[a][0] * inv; o.y = acc[a][1] * inv;
        o.z = acc[a][2] * inv; o.w = acc[a][3] * inv;
        *(float4*)&g_y[((size_t)b * TT + q0 + row) * CB + h * DH + ld * 4] = o;
    }
}

// ---------------------------------------------------------------------------
extern "C" void kernel_launch(void* const* d_in, const int* in_sizes, int n_in,
                              void* d_out, int out_size)
{
    (void)in_sizes; (void)n_in; (void)out_size;
    const float* x      = (const float*)d_in[0];
    const float* w_qkv  = (const float*)d_in[1];
    const float* b_qkv  = (const float*)d_in[2];
    const float* w_proj = (const float*)d_in[3];
    const float* b_proj = (const float*)d_in[4];
    float* out = (float*)d_out;

    cudaFuncSetAttribute(tgemm<1>, cudaFuncAttributeMaxDynamicSharedMemorySize, TG_SMEM);
    cudaFuncSetAttribute(tgemm<0>, cudaFuncAttributeMaxDynamicSharedMemorySize, TG_SMEM);
    cudaFuncSetAttribute(attn2,    cudaFuncAttributeMaxDynamicSharedMemorySize, ATTN_SMEM);

    // 0) bf16 hi/lo splits of activations + transposed weight splits
    split_x<<<(MTOT * CB / 4) / 256, 256>>>((const float4*)x);
    transpose_split<0><<<dim3(N_QKV / 32, CB / 32), dim3(32, 8)>>>(w_qkv, CB, N_QKV);
    transpose_split<1><<<dim3(CB / 32, CB / 32), dim3(32, 8)>>>(w_proj, CB, CB);

    // 1) QKV GEMM (bf16x3 tensor) with scatter epilogue -> g_q/g_k/g_kT/g_v
    tgemm<1><<<dim3(N_QKV / 128, MTOT / 128), 256, TG_SMEM>>>(b_qkv, nullptr, N_QKV, CB);

    // 2) Tiled sparse causal attention -> g_y
    attn2<<<dim3(TT / 64, NH, BBATCH), 256, ATTN_SMEM>>>();

    // 3) split y, then output projection GEMM -> d_out
    split_y<<<(MTOT * CB / 4) / 256, 256>>>();
    tgemm<0><<<dim3(CB / 128, MTOT / 128), 256, TG_SMEM>>>(b_proj, out, CB, CB);
}

// round 7
// speedup vs baseline: 1.9067x; 1.1238x over previous
#include <cuda_runtime.h>
#include <cuda_bf16.h>
#include <math.h>
#include <stdint.h>

// Problem constants (fixed shapes from reference setup_inputs)
#define CB      1024      // n_embd
#define NH      16        // heads
#define DH      64        // head dim
#define TT      4096      // seq len
#define BBATCH  2         // batch
#define WINDOW  256
#define STRIDE  128
#define NGLOB   16

#define MTOT    (BBATCH*TT)          // 8192
#define N_QKV   (3*CB)               // 3072

// ---------------------------------------------------------------------------
// Scratch (device globals: allocation-free per harness rules)
// ---------------------------------------------------------------------------
__device__ float g_q [BBATCH*NH*TT*DH];   // [b,h,t,d] fp32
__device__ float g_k [BBATCH*NH*TT*DH];   // fp32 (serial path)
__device__ float g_v [BBATCH*NH*TT*DH];   // fp32 (serial path)
__device__ float g_y [BBATCH*TT*CB];      // [b,t,c] attention output

__device__ __align__(128) __nv_bfloat16 g_khi[BBATCH*NH*TT*DH];
__device__ __align__(128) __nv_bfloat16 g_klo[BBATCH*NH*TT*DH];
__device__ __align__(128) __nv_bfloat16 g_vhi[BBATCH*NH*TT*DH];
__device__ __align__(128) __nv_bfloat16 g_vlo[BBATCH*NH*TT*DH];

__device__ __align__(128) __nv_bfloat16 g_xhi[MTOT*CB];     // bf16-hi of x
__device__ __align__(128) __nv_bfloat16 g_xlo[MTOT*CB];     // bf16-lo of x
__device__ __align__(128) __nv_bfloat16 g_yhi[MTOT*CB];
__device__ __align__(128) __nv_bfloat16 g_ylo[MTOT*CB];
__device__ __align__(128) __nv_bfloat16 g_wqT_hi[N_QKV*CB]; // w_qkv^T [N,K]
__device__ __align__(128) __nv_bfloat16 g_wqT_lo[N_QKV*CB];
__device__ __align__(128) __nv_bfloat16 g_wpT_hi[CB*CB];    // w_proj^T [N,K]
__device__ __align__(128) __nv_bfloat16 g_wpT_lo[CB*CB];

// ---------------------------------------------------------------------------
// PTX helpers (all sm_80+ portable: cp.async / ldmatrix / mma.sync)
// ---------------------------------------------------------------------------
__device__ __forceinline__ uint32_t su32(const void* p) {
    return (uint32_t)__cvta_generic_to_shared(p);
}
__device__ __forceinline__ void cpa16(uint32_t s, const void* g) {
    asm volatile("cp.async.cg.shared.global [%0], [%1], 16;\n" :: "r"(s), "l"(g));
}
__device__ __forceinline__ void cpa_commit() {
    asm volatile("cp.async.commit_group;\n" ::);
}
template <int NW> __device__ __forceinline__ void cpa_wait() {
    asm volatile("cp.async.wait_group %0;\n" :: "n"(NW));
}
__device__ __forceinline__ void ldm_x4(uint32_t* r, uint32_t addr) {
    asm volatile("ldmatrix.sync.aligned.m8n8.x4.shared.b16 {%0,%1,%2,%3}, [%4];"
                 : "=r"(r[0]), "=r"(r[1]), "=r"(r[2]), "=r"(r[3]) : "r"(addr));
}
__device__ __forceinline__ void ldm_x4t(uint32_t* r, uint32_t addr) {
    asm volatile("ldmatrix.sync.aligned.m8n8.x4.trans.shared.b16 {%0,%1,%2,%3}, [%4];"
                 : "=r"(r[0]), "=r"(r[1]), "=r"(r[2]), "=r"(r[3]) : "r"(addr));
}
__device__ __forceinline__ void ldm_x2(uint32_t* r, uint32_t addr) {
    asm volatile("ldmatrix.sync.aligned.m8n8.x2.shared.b16 {%0,%1}, [%2];"
                 : "=r"(r[0]), "=r"(r[1]) : "r"(addr));
}
__device__ __forceinline__ void mma16816(float* c, const uint32_t* a, const uint32_t* b) {
    asm volatile("mma.sync.aligned.m16n8k16.row.col.f32.bf16.bf16.f32 "
                 "{%0,%1,%2,%3}, {%4,%5,%6,%7}, {%8,%9}, {%0,%1,%2,%3};"
                 : "+f"(c[0]), "+f"(c[1]), "+f"(c[2]), "+f"(c[3])
                 : "r"(a[0]), "r"(a[1]), "r"(a[2]), "r"(a[3]), "r"(b[0]), "r"(b[1]));
}
__device__ __forceinline__ __nv_bfloat16 bf_hi(float x) { return __float2bfloat16_rn(x); }

// ---------------------------------------------------------------------------
// Preprocessing: bf16 hi/lo splits and transpose-splits
// ---------------------------------------------------------------------------
__global__ void split_x(const float4* __restrict__ src) {
    int i = blockIdx.x * blockDim.x + threadIdx.x;   // MTOT*CB/4 threads
    float4 v = src[i];
    __nv_bfloat162 h01, h23, l01, l23;
    h01.x = bf_hi(v.x); l01.x = bf_hi(v.x - __bfloat162float(h01.x));
    h01.y = bf_hi(v.y); l01.y = bf_hi(v.y - __bfloat162float(h01.y));
    h23.x = bf_hi(v.z); l23.x = bf_hi(v.z - __bfloat162float(h23.x));
    h23.y = bf_hi(v.w); l23.y = bf_hi(v.w - __bfloat162float(h23.y));
    ((__nv_bfloat162*)g_xhi)[2 * i]     = h01;
    ((__nv_bfloat162*)g_xhi)[2 * i + 1] = h23;
    ((__nv_bfloat162*)g_xlo)[2 * i]     = l01;
    ((__nv_bfloat162*)g_xlo)[2 * i + 1] = l23;
}
__global__ void split_y() {
    int i = blockIdx.x * blockDim.x + threadIdx.x;
    float4 v = ((const float4*)g_y)[i];
    __nv_bfloat162 h01, h23, l01, l23;
    h01.x = bf_hi(v.x); l01.x = bf_hi(v.x - __bfloat162float(h01.x));
    h01.y = bf_hi(v.y); l01.y = bf_hi(v.y - __bfloat162float(h01.y));
    h23.x = bf_hi(v.z); l23.x = bf_hi(v.z - __bfloat162float(h23.x));
    h23.y = bf_hi(v.w); l23.y = bf_hi(v.w - __bfloat162float(h23.y));
    ((__nv_bfloat162*)g_yhi)[2 * i]     = h01;
    ((__nv_bfloat162*)g_yhi)[2 * i + 1] = h23;
    ((__nv_bfloat162*)g_ylo)[2 * i]     = l01;
    ((__nv_bfloat162*)g_ylo)[2 * i + 1] = l23;
}
// W [K,N] row-major -> WT_hi/WT_lo [N,K] bf16
template <int SEL>
__global__ void transpose_split(const float* __restrict__ W, int K, int N) {
    __nv_bfloat16* Thi = (SEL == 0) ? g_wqT_hi : g_wpT_hi;
    __nv_bfloat16* Tlo = (SEL == 0) ? g_wqT_lo : g_wpT_lo;
    __shared__ float t[32][33];
    const int n0 = blockIdx.x * 32, k0 = blockIdx.y * 32;
    const int tx = threadIdx.x, ty = threadIdx.y;
    #pragma unroll
    for (int r = ty; r < 32; r += 8)
        t[r][tx] = W[(size_t)(k0 + r) * N + n0 + tx];
    __syncthreads();
    #pragma unroll
    for (int r = ty; r < 32; r += 8) {
        float v = t[tx][r];
        __nv_bfloat16 h = bf_hi(v);
        __nv_bfloat16 l = bf_hi(v - __bfloat162float(h));
        size_t o = (size_t)(n0 + r) * K + k0 + tx;
        Thi[o] = h;
        Tlo[o] = l;
    }
}

// ---------------------------------------------------------------------------
// bf16x3 tensor-core GEMM via mma.sync.m16n8k16.
// MODE 1 epilogue: q/k/v fp32 + k/v bf16 hi/lo (for HMMA attention).
// ---------------------------------------------------------------------------
#define ST_BYTES  32768                 // per stage: Ahi|Alo|Bhi|Blo, 8KB each
#define TG_SMEM   (3*ST_BYTES)

template <int MODE>
__global__ void __launch_bounds__(256, 1)
tgemm(const float* __restrict__ bias, float* __restrict__ C, int N, int K)
{
    extern __shared__ __align__(128) unsigned char smbuf[];
    const uint32_t sbase = su32(smbuf);
    const int tid = threadIdx.x;
    const int bm = blockIdx.y * 128;
    const int bn = blockIdx.x * 128;

    const __nv_bfloat16* __restrict__ Ahi = (MODE == 1) ? g_xhi : g_yhi;
    const __nv_bfloat16* __restrict__ Alo = (MODE == 1) ? g_xlo : g_ylo;
    const __nv_bfloat16* __restrict__ Bhi = (MODE == 1) ? g_wqT_hi : g_wpT_hi;
    const __nv_bfloat16* __restrict__ Blo = (MODE == 1) ? g_wqT_lo : g_wpT_lo;

    const int NK = K / 32;   // 32

    const int ldrow = tid >> 1;
    const int ldc0  = (tid & 1) * 2;
    auto load_stage = [&](int stage, int k0) {
        const uint32_t sb = sbase + (uint32_t)stage * ST_BYTES;
        #pragma unroll
        for (int cc = 0; cc < 2; cc++) {
            const int c = ldc0 + cc;
            const uint32_t so = (uint32_t)(ldrow * 64 + ((c ^ ((ldrow >> 1) & 3)) << 4));
            const size_t ga = (size_t)(bm + ldrow) * K + k0 + c * 8;
            const size_t gb = (size_t)(bn + ldrow) * K + k0 + c * 8;
            cpa16(sb + so,               Ahi + ga);
            cpa16(sb + 8192 + so,        Alo + ga);
            cpa16(sb + 16384 + so,       Bhi + gb);
            cpa16(sb + 24576 + so,       Blo + gb);
        }
        cpa_commit();
    };

    load_stage(0, 0);
    load_stage(1, 32);

    const int lane = tid & 31, w = tid >> 5;
    const int wm = w >> 2, wn = w & 3;
    const int a_r = lane & 15, a_c = lane >> 4;
    const int b_r = lane & 7,  b_c = (lane >> 3) & 1;

    float acc[4][4][4];
    #pragma unroll
    for (int mt = 0; mt < 4; mt++)
        #pragma unroll
        for (int nt = 0; nt < 4; nt++)
            #pragma unroll
            for (int q = 0; q < 4; q++) acc[mt][nt][q] = 0.f;

    for (int ks = 0; ks < NK; ks++) {
        if (ks == NK - 1) cpa_wait<0>(); else cpa_wait<1>();
        __syncthreads();
        if (ks + 2 < NK) load_stage((ks + 2) % 3, (ks + 2) * 32);

        const uint32_t sb = sbase + (uint32_t)(ks % 3) * ST_BYTES;
        #pragma unroll
        for (int t = 0; t < 2; t++) {
            uint32_t ah[4][4], al[4][4], bh[4][2], bl[4][2];
            #pragma unroll
            for (int mt = 0; mt < 4; mt++) {
                const int r = wm * 64 + mt * 16 + a_r;
                const int c = t * 2 + a_c;
                const uint32_t so = (uint32_t)(r * 64 + ((c ^ ((r >> 1) & 3)) << 4));
                ldm_x4(ah[mt], sb + so);
                ldm_x4(al[mt], sb + 8192 + so);
            }
            #pragma unroll
            for (int nt = 0; nt < 4; nt++) {
                const int r = wn * 32 + nt * 8 + b_r;
                const int c = t * 2 + b_c;
                const uint32_t so = (uint32_t)(r * 64 + ((c ^ ((r >> 1) & 3)) << 4));
                ldm_x2(bh[nt], sb + 16384 + so);
                ldm_x2(bl[nt], sb + 24576 + so);
            }
            #pragma unroll
            for (int mt = 0; mt < 4; mt++)
                #pragma unroll
                for (int nt = 0; nt < 4; nt++) {
                    mma16816(acc[mt][nt], ah[mt], bh[nt]);
                    mma16816(acc[mt][nt], ah[mt], bl[nt]);
                    mma16816(acc[mt][nt], al[mt], bh[nt]);
                }
        }
        __syncthreads();
    }

    const int colq = (lane & 3) * 2;
    const int rowq = lane >> 2;
    #pragma unroll
    for (int nt = 0; nt < 4; nt++) {
        const int cg = bn + wn * 32 + nt * 8 + colq;
        const float b0 = bias[cg], b1 = bias[cg + 1];
        #pragma unroll
        for (int mt = 0; mt < 4; mt++) {
            const int r0 = bm + wm * 64 + mt * 16 + rowq;
            const int r1 = r0 + 8;
            float v00 = acc[mt][nt][0] + b0, v01 = acc[mt][nt][1] + b1;
            float v10 = acc[mt][nt][2] + b0, v11 = acc[mt][nt][3] + b1;
            if (MODE == 0) {
                *(float2*)(C + (size_t)r0 * N + cg) = make_float2(v00, v01);
                *(float2*)(C + (size_t)r1 * N + cg) = make_float2(v10, v11);
            } else {
                const int sec = cg >> 10;            // 0=q,1=k,2=v
                const int f  = cg & 1023;
                const int hh = f >> 6, d0 = f & 63;  // d0 even
                #pragma unroll
                for (int rr = 0; rr < 2; rr++) {
                    const int mrow = rr ? r1 : r0;
                    const float va = rr ? v10 : v00;
                    const float vb = rr ? v11 : v01;
                    const int bidx = mrow >> 12;
                    const int ttk  = mrow & (TT - 1);
                    const int bh2  = bidx * NH + hh;
                    const size_t base = ((size_t)bh2 * TT + ttk) * DH + d0;
                    if (sec == 0) {
                        *(float2*)(g_q + base) = make_float2(va, vb);
                    } else {
                        float* dst = (sec == 1) ? g_k : g_v;
                        *(float2*)(dst + base) = make_float2(va, vb);
                        __nv_bfloat162 h2, l2;
                        h2.x = bf_hi(va); h2.y = bf_hi(vb);
                        l2.x = bf_hi(va - __bfloat162float(h2.x));
                        l2.y = bf_hi(vb - __bfloat162float(h2.y));
                        __nv_bfloat162* dh = (sec == 1) ? (__nv_bfloat162*)g_khi
                                                        : (__nv_bfloat162*)g_vhi;
                        __nv_bfloat162* dl = (sec == 1) ? (__nv_bfloat162*)g_klo
                                                        : (__nv_bfloat162*)g_vlo;
                        dh[base >> 1] = h2;
                        dl[base >> 1] = l2;
                    }
                }
            }
        }
    }
}

// ---------------------------------------------------------------------------
// HMMA flash sparse attention. CTA = 64 queries x (b,h), 8 warps =
// 4 qgroups x 2 kgroups. Scores bf16x3 (Q,K hi/lo), PV bf16x3 (P,V hi/lo).
// K/V tiles loaded as bf16 hi/lo directly (written by tgemm<1> epilogue).
// Per-warp partial O over its 32 keys; merged row-split at the end; far
// stride keys (j <= i-384) handled serially on merged fragments.
// ---------------------------------------------------------------------------
#define AT_QHI   0
#define AT_QLO   8192
#define AT_KV    16384                 // 2 bufs x 4 tiles x 8KB = 64KB
#define AT_MRG   AT_KV                 // merge buffer reuses KV area (16KB)
#define AT_STAT  (AT_KV + 65536)       // 81920: m[64] l[64] pmax[128] psum[128]
#define ATTN3_SMEM (AT_STAT + 384*4)   // 83456

__global__ void __launch_bounds__(256, 2)
attn3()
{
    extern __shared__ __align__(16) unsigned char smb[];
    const uint32_t sb = su32(smb);
    float* stat = (float*)(smb + AT_STAT);   // [0:64) m, [64:128) l
    float* pmax = stat + 128;                // [2][64]
    float* psum = stat + 256;                // [2][64]

    const int tid  = threadIdx.x;
    const int lane = tid & 31;
    const int w    = tid >> 5;
    const int qg   = w >> 1, kg = w & 1;
    const int rbase = qg * 16;
    const int colbase = kg * 32;
    const int q0 = blockIdx.x * 64;
    const int h  = blockIdx.y;
    const int b  = blockIdx.z;
    const int bh = b * NH + h;

    // ---- load Q fp32 -> bf16 hi/lo smem tiles (chunk-swizzled) ----
    {
        const float* qsrc = g_q + ((size_t)bh * TT + q0) * DH;
        #pragma unroll
        for (int it = 0; it < 2; it++) {
            const int id = tid + it * 256;       // 0..511
            const int row = id >> 3, c = id & 7;
            const float4 f0 = *(const float4*)(qsrc + (size_t)row * DH + c * 8);
            const float4 f1 = *(const float4*)(qsrc + (size_t)row * DH + c * 8 + 4);
            float vv[8] = {f0.x, f0.y, f0.z, f0.w, f1.x, f1.y, f1.z, f1.w};
            __nv_bfloat162 hh[4], ll[4];
            #pragma unroll
            for (int u = 0; u < 4; u++) {
                hh[u].x = bf_hi(vv[2*u]);   hh[u].y = bf_hi(vv[2*u+1]);
                ll[u].x = bf_hi(vv[2*u]   - __bfloat162float(hh[u].x));
                ll[u].y = bf_hi(vv[2*u+1] - __bfloat162float(hh[u].y));
            }
            const uint32_t off = (uint32_t)(row * 128 + ((c ^ (row & 7)) << 4));
            *(uint4*)(smb + AT_QHI + off) = *(uint4*)hh;
            *(uint4*)(smb + AT_QLO + off) = *(uint4*)ll;
        }
        if (tid < 64) { stat[tid] = -INFINITY; stat[64 + tid] = 0.f; }
    }

    // ---- key-block schedule ----
    const int kstart = (q0 > 256) ? (q0 - 256) : 0;
    const int extra  = (kstart > 0) ? 1 : 0;
    const int nb     = (q0 + 64 - kstart) / 64 + extra;
    auto kb_of = [&](int bi) -> int {
        return (extra && bi == 0) ? 0 : kstart + (bi - extra) * 64;
    };

    auto load_kv = [&](int bufn, int kb) {
        const size_t gb = ((size_t)bh * TT + kb) * DH;
        const __nv_bfloat16* srcs[4] = {g_khi + gb, g_klo + gb, g_vhi + gb, g_vlo + gb};
        const uint32_t dst0 = sb + AT_KV + (uint32_t)bufn * 32768;
        #pragma unroll
        for (int qq = 0; qq < 8; qq++) {
            const int tile = qq >> 1;
            const int within = tid + (qq & 1) * 256;   // 0..511
            const int row = within >> 3, c = within & 7;
            cpa16(dst0 + tile * 8192 + row * 128 + ((c ^ (row & 7)) << 4),
                  srcs[tile] + (size_t)row * DH + c * 8);
        }
        cpa_commit();
    };

    load_kv(0, kb_of(0));

    float o[8][4];
    #pragma unroll
    for (int nt = 0; nt < 8; nt++)
        #pragma unroll
        for (int e = 0; e < 4; e++) o[nt][e] = 0.f;

    const int quad_lo = (lane >> 3) & 1;   // for Q/V addressing
    const int quad_hi = lane >> 4;
    const int l7 = lane & 7;
    const int rl = rbase + (lane >> 2);    // fragment low row

    __syncthreads();

    for (int bi = 0; bi < nb; bi++) {
        const int kb  = kb_of(bi);
        const int buf = bi & 1;
        const bool gonly = (extra && bi == 0);

        if (bi + 1 < nb) { load_kv(buf ^ 1, kb_of(bi + 1)); cpa_wait<1>(); }
        else             { cpa_wait<0>(); }
        __syncthreads();

        const uint32_t kvb = sb + AT_KV + (uint32_t)buf * 32768;

        // ---- scores: S[16q x 32k] per warp, bf16x3 ----
        float s[4][4];
        #pragma unroll
        for (int nt = 0; nt < 4; nt++)
            #pragma unroll
            for (int e = 0; e < 4; e++) s[nt][e] = 0.f;

        #pragma unroll
        for (int ks = 0; ks < 4; ks++) {
            uint32_t qh[4], ql[4];
            {
                const int row = rbase + quad_lo * 8 + l7;
                const int ch  = 2 * ks + quad_hi;
                const uint32_t off = (uint32_t)(row * 128 + ((ch ^ (row & 7)) << 4));
                ldm_x4(qh, sb + AT_QHI + off);
                ldm_x4(ql, sb + AT_QLO + off);
            }
            #pragma unroll
            for (int ntp = 0; ntp < 2; ntp++) {
                uint32_t kh[4], kl[4];
                const int rowk = colbase + ntp * 16 + quad_hi * 8 + l7;
                const int chk  = 2 * ks + quad_lo;
                const uint32_t offk = (uint32_t)(rowk * 128 + ((chk ^ (rowk & 7)) << 4));
                ldm_x4(kh, kvb + offk);            // KHI tile at +0
                ldm_x4(kl, kvb + 8192 + offk);     // KLO tile
                mma16816(s[2*ntp],   qh, kh);
                mma16816(s[2*ntp],   qh, kl);
                mma16816(s[2*ntp],   ql, kh);
                mma16816(s[2*ntp+1], qh, kh + 2);
                mma16816(s[2*ntp+1], qh, kl + 2);
                mma16816(s[2*ntp+1], ql, kh + 2);
            }
        }

        // ---- mask + scale ----
        #pragma unroll
        for (int nt = 0; nt < 4; nt++)
            #pragma unroll
            for (int e = 0; e < 4; e++) {
                const int row = rl + (e >> 1) * 8;
                const int i = q0 + row;
                const int j = kb + colbase + nt * 8 + 2 * (lane & 3) + (e & 1);
                const int dij = i - j;
                const bool ok = gonly ? (j < NGLOB)
                    : (dij >= 0 && (dij < WINDOW || (dij & (STRIDE - 1)) == 0 || j < NGLOB));
                s[nt][e] = ok ? s[nt][e] * 0.125f : -INFINITY;
            }

        // ---- partial row max (warp's 32 cols) ----
        float mx0 = fmaxf(fmaxf(s[0][0], s[0][1]), fmaxf(s[1][0], s[1][1]));
        mx0 = fmaxf(mx0, fmaxf(fmaxf(s[2][0], s[2][1]), fmaxf(s[3][0], s[3][1])));
        float mx1 = fmaxf(fmaxf(s[0][2], s[0][3]), fmaxf(s[1][2], s[1][3]));
        mx1 = fmaxf(mx1, fmaxf(fmaxf(s[2][2], s[2][3]), fmaxf(s[3][2], s[3][3])));
        mx0 = fmaxf(mx0, __shfl_xor_sync(0xffffffffu, mx0, 1));
        mx0 = fmaxf(mx0, __shfl_xor_sync(0xffffffffu, mx0, 2));
        mx1 = fmaxf(mx1, __shfl_xor_sync(0xffffffffu, mx1, 1));
        mx1 = fmaxf(mx1, __shfl_xor_sync(0xffffffffu, mx1, 2));
        if ((lane & 3) == 0) {
            pmax[kg * 64 + rl]     = mx0;
            pmax[kg * 64 + rl + 8] = mx1;
        }
        __syncthreads();

        const float m0 = stat[rl], m1 = stat[rl + 8];
        const float mn0 = fmaxf(m0, fmaxf(pmax[rl],     pmax[64 + rl]));
        const float mn1 = fmaxf(m1, fmaxf(pmax[rl + 8], pmax[64 + rl + 8]));
        const float al0 = __expf(m0 - mn0);
        const float al1 = __expf(m1 - mn1);

        float sum0 = 0.f, sum1 = 0.f;
        #pragma unroll
        for (int nt = 0; nt < 4; nt++) {
            s[nt][0] = __expf(s[nt][0] - mn0); sum0 += s[nt][0];
            s[nt][1] = __expf(s[nt][1] - mn0); sum0 += s[nt][1];
            s[nt][2] = __expf(s[nt][2] - mn1); sum1 += s[nt][2];
            s[nt][3] = __expf(s[nt][3] - mn1); sum1 += s[nt][3];
        }
        sum0 += __shfl_xor_sync(0xffffffffu, sum0, 1);
        sum0 += __shfl_xor_sync(0xffffffffu, sum0, 2);
        sum1 += __shfl_xor_sync(0xffffffffu, sum1, 1);
        sum1 += __shfl_xor_sync(0xffffffffu, sum1, 2);
        if ((lane & 3) == 0) {
            psum[kg * 64 + rl]     = sum0;
            psum[kg * 64 + rl + 8] = sum1;
        }
        __syncthreads();

        if (kg == 0 && (lane & 3) == 0) {
            stat[rl] = mn0; stat[rl + 8] = mn1;
            stat[64 + rl]     = stat[64 + rl]     * al0 + psum[rl]     + psum[64 + rl];
            stat[64 + rl + 8] = stat[64 + rl + 8] * al1 + psum[rl + 8] + psum[64 + rl + 8];
        }

        // ---- rescale O ----
        #pragma unroll
        for (int nt = 0; nt < 8; nt++) {
            o[nt][0] *= al0; o[nt][1] *= al0;
            o[nt][2] *= al1; o[nt][3] *= al1;
        }

        // ---- PV: P (hi/lo) x V (hi/lo), 3 combos ----
        #pragma unroll
        for (int ks2 = 0; ks2 < 2; ks2++) {
            const int t0 = 2 * ks2, t1 = t0 + 1;
            uint32_t pah[4], pal[4];
            {
                __nv_bfloat162 h2, l2;
                #pragma unroll
                for (int u = 0; u < 4; u++) {
                    const int tt = (u < 2) ? t0 : t1;
                    const int e0 = (u & 1) * 2;
                    const float p0 = s[tt][e0], p1 = s[tt][e0 + 1];
                    h2.x = bf_hi(p0); h2.y = bf_hi(p1);
                    l2.x = bf_hi(p0 - __bfloat162float(h2.x));
                    l2.y = bf_hi(p1 - __bfloat162float(h2.y));
                    pah[u] = *(uint32_t*)&h2;
                    pal[u] = *(uint32_t*)&l2;
                }
            }
            const int kb2 = colbase + ks2 * 16;
            #pragma unroll
            for (int ntp = 0; ntp < 4; ntp++) {
                uint32_t vh[4], vl[4];
                const int rowv = kb2 + quad_lo * 8 + l7;
                const int chv  = 2 * ntp + quad_hi;
                const uint32_t offv = (uint32_t)(rowv * 128 + ((chv ^ (rowv & 7)) << 4));
                ldm_x4t(vh, kvb + 16384 + offv);   // VHI tile
                ldm_x4t(vl, kvb + 24576 + offv);   // VLO tile
                mma16816(o[2*ntp],   pah, vh);
                mma16816(o[2*ntp],   pah, vl);
                mma16816(o[2*ntp],   pal, vh);
                mma16816(o[2*ntp+1], pah, vh + 2);
                mma16816(o[2*ntp+1], pah, vl + 2);
                mma16816(o[2*ntp+1], pal, vh + 2);
            }
        }
        __syncthreads();
    }

    // ---- merge partial O: kg0 keeps rows 0-7, kg1 keeps rows 8-15 ----
    float* mrg = (float*)(smb + AT_MRG);   // [qg][16][64]
    {
        const int wr = (kg == 0) ? (lane >> 2) + 8 : (lane >> 2);
        float* basep = mrg + (qg * 16 + wr) * 64;
        const int c0 = kg ? 0 : 2;
        #pragma unroll
        for (int nt = 0; nt < 8; nt++) {
            basep[nt * 8 + 2 * (lane & 3)]     = o[nt][c0];
            basep[nt * 8 + 2 * (lane & 3) + 1] = o[nt][c0 + 1];
        }
    }
    __syncthreads();
    {
        const int rd = (kg == 0) ? (lane >> 2) : (lane >> 2) + 8;
        const float* basep = mrg + (qg * 16 + rd) * 64;
        const int c0 = kg ? 2 : 0;
        #pragma unroll
        for (int nt = 0; nt < 8; nt++) {
            o[nt][c0]     += basep[nt * 8 + 2 * (lane & 3)];
            o[nt][c0 + 1] += basep[nt * 8 + 2 * (lane & 3) + 1];
        }
    }

    // ---- serial far-stride keys on merged fragments ----
    const int ce0 = kg ? 2 : 0;
    #pragma unroll 1
    for (int t = 0; t < 8; t++) {
        const int row = rbase + (kg ? 8 : 0) + t;
        const int i = q0 + row;
        int j = i - 3 * STRIDE;
        if (j >= NGLOB) {
            float m_r = stat[row], l_r = stat[64 + row];
            float q_l, q_h;
            {
                const uint32_t offA = (uint32_t)(row * 128 + (((lane >> 3) ^ (row & 7)) << 4) + (lane & 7) * 2);
                const int d2 = lane + 32;
                const uint32_t offB = (uint32_t)(row * 128 + (((d2 >> 3) ^ (row & 7)) << 4) + (d2 & 7) * 2);
                q_l = __bfloat162float(*(__nv_bfloat16*)(smb + AT_QHI + offA))
                    + __bfloat162float(*(__nv_bfloat16*)(smb + AT_QLO + offA));
                q_h = __bfloat162float(*(__nv_bfloat16*)(smb + AT_QHI + offB))
                    + __bfloat162float(*(__nv_bfloat16*)(smb + AT_QLO + offB));
            }
            const bool own = ((lane >> 2) == t);
            for (; j >= NGLOB; j -= STRIDE) {
                const float* kr = g_k + ((size_t)bh * TT + j) * DH;
                float part = q_l * kr[lane] + q_h * kr[lane + 32];
                #pragma unroll
                for (int off = 16; off; off >>= 1)
                    part += __shfl_xor_sync(0xffffffffu, part, off);
                const float sv = part * 0.125f;
                const float mnew = fmaxf(m_r, sv);
                const float alpha = __expf(m_r - mnew);
                const float p = __expf(sv - mnew);
                l_r = l_r * alpha + p;
                m_r = mnew;
                if (own) {
                    const float* vr = g_v + ((size_t)bh * TT + j) * DH;
                    #pragma unroll
                    for (int nt = 0; nt < 8; nt++) {
                        const float2 vv = *(const float2*)(vr + nt * 8 + 2 * (lane & 3));
                        o[nt][ce0]     = o[nt][ce0]     * alpha + p * vv.x;
                        o[nt][ce0 + 1] = o[nt][ce0 + 1] * alpha + p * vv.y;
                    }
                }
            }
            if (lane == 0) stat[64 + row] = l_r;
            __syncwarp();
        }
    }

    // ---- normalize + write y ----
    {
        const int row = rbase + (kg ? 8 : 0) + (lane >> 2);
        const float inv = 1.f / stat[64 + row];
        float* yr = g_y + ((size_t)b * TT + q0 + row) * CB + h * DH;
        #pragma unroll
        for (int nt = 0; nt < 8; nt++)
            *(float2*)(yr + nt * 8 + 2 * (lane & 3)) =
                make_float2(o[nt][ce0] * inv, o[nt][ce0 + 1] * inv);
    }
}

// ---------------------------------------------------------------------------
extern "C" void kernel_launch(void* const* d_in, const int* in_sizes, int n_in,
                              void* d_out, int out_size)
{
    (void)in_sizes; (void)n_in; (void)out_size;
    const float* x      = (const float*)d_in[0];
    const float* w_qkv  = (const float*)d_in[1];
    const float* b_qkv  = (const float*)d_in[2];
    const float* w_proj = (const float*)d_in[3];
    const float* b_proj = (const float*)d_in[4];
    float* out = (float*)d_out;

    cudaFuncSetAttribute(tgemm<1>, cudaFuncAttributeMaxDynamicSharedMemorySize, TG_SMEM);
    cudaFuncSetAttribute(tgemm<0>, cudaFuncAttributeMaxDynamicSharedMemorySize, TG_SMEM);
    cudaFuncSetAttribute(attn3,    cudaFuncAttributeMaxDynamicSharedMemorySize, ATTN3_SMEM);

    // 0) bf16 hi/lo splits of activations + transposed weight splits
    split_x<<<(MTOT * CB / 4) / 256, 256>>>((const float4*)x);
    transpose_split<0><<<dim3(N_QKV / 32, CB / 32), dim3(32, 8)>>>(w_qkv, CB, N_QKV);
    transpose_split<1><<<dim3(CB / 32, CB / 32), dim3(32, 8)>>>(w_proj, CB, CB);

    // 1) QKV GEMM -> q/k/v fp32 + k/v bf16 hi/lo
    tgemm<1><<<dim3(N_QKV / 128, MTOT / 128), 256, TG_SMEM>>>(b_qkv, nullptr, N_QKV, CB);

    // 2) HMMA flash sparse attention -> g_y
    attn3<<<dim3(TT / 64, NH, BBATCH), 256, ATTN3_SMEM>>>();

    // 3) split y, then output projection GEMM -> d_out
    split_y<<<(MTOT * CB / 4) / 256, 256>>>();
    tgemm<0><<<dim3(CB / 128, MTOT / 128), 256, TG_SMEM>>>(b_proj, out, CB, CB);
}

// round 8
// speedup vs baseline: 2.6843x; 1.4078x over previous
#include <cuda_runtime.h>
#include <cuda_bf16.h>
#include <math.h>
#include <stdint.h>

// Problem constants (fixed shapes from reference setup_inputs)
#define CB      1024      // n_embd
#define NH      16        // heads
#define DH      64        // head dim
#define TT      4096      // seq len
#define BBATCH  2         // batch
#define WINDOW  256
#define STRIDE  128
#define NGLOB   16

#define MTOT    (BBATCH*TT)          // 8192
#define N_QKV   (3*CB)               // 3072

// ---------------------------------------------------------------------------
// Scratch (device globals: allocation-free per harness rules)
// ---------------------------------------------------------------------------
__device__ float g_q [BBATCH*NH*TT*DH];   // [b,h,t,d] fp32
__device__ float g_k [BBATCH*NH*TT*DH];   // fp32 (diagonal path)
__device__ float g_v [BBATCH*NH*TT*DH];   // fp32 (diagonal path)
__device__ float g_y [BBATCH*TT*CB];      // [b,t,c] attention output

__device__ __align__(128) __nv_bfloat16 g_khi[BBATCH*NH*TT*DH];
__device__ __align__(128) __nv_bfloat16 g_klo[BBATCH*NH*TT*DH];
__device__ __align__(128) __nv_bfloat16 g_vhi[BBATCH*NH*TT*DH];
__device__ __align__(128) __nv_bfloat16 g_vlo[BBATCH*NH*TT*DH];

__device__ __align__(128) __nv_bfloat16 g_xhi[MTOT*CB];     // bf16-hi of x
__device__ __align__(128) __nv_bfloat16 g_xlo[MTOT*CB];     // bf16-lo of x
__device__ __align__(128) __nv_bfloat16 g_yhi[MTOT*CB];
__device__ __align__(128) __nv_bfloat16 g_ylo[MTOT*CB];
__device__ __align__(128) __nv_bfloat16 g_wqT_hi[N_QKV*CB]; // w_qkv^T [N,K]
__device__ __align__(128) __nv_bfloat16 g_wqT_lo[N_QKV*CB];
__device__ __align__(128) __nv_bfloat16 g_wpT_hi[CB*CB];    // w_proj^T [N,K]
__device__ __align__(128) __nv_bfloat16 g_wpT_lo[CB*CB];

// ---------------------------------------------------------------------------
// PTX helpers (all sm_80+ portable: cp.async / ldmatrix / mma.sync)
// ---------------------------------------------------------------------------
__device__ __forceinline__ uint32_t su32(const void* p) {
    return (uint32_t)__cvta_generic_to_shared(p);
}
__device__ __forceinline__ void cpa16(uint32_t s, const void* g) {
    asm volatile("cp.async.cg.shared.global [%0], [%1], 16;\n" :: "r"(s), "l"(g));
}
__device__ __forceinline__ void cpa_commit() {
    asm volatile("cp.async.commit_group;\n" ::);
}
template <int NW> __device__ __forceinline__ void cpa_wait() {
    asm volatile("cp.async.wait_group %0;\n" :: "n"(NW));
}
__device__ __forceinline__ void ldm_x4(uint32_t* r, uint32_t addr) {
    asm volatile("ldmatrix.sync.aligned.m8n8.x4.shared.b16 {%0,%1,%2,%3}, [%4];"
                 : "=r"(r[0]), "=r"(r[1]), "=r"(r[2]), "=r"(r[3]) : "r"(addr));
}
__device__ __forceinline__ void ldm_x4t(uint32_t* r, uint32_t addr) {
    asm volatile("ldmatrix.sync.aligned.m8n8.x4.trans.shared.b16 {%0,%1,%2,%3}, [%4];"
                 : "=r"(r[0]), "=r"(r[1]), "=r"(r[2]), "=r"(r[3]) : "r"(addr));
}
__device__ __forceinline__ void ldm_x2(uint32_t* r, uint32_t addr) {
    asm volatile("ldmatrix.sync.aligned.m8n8.x2.shared.b16 {%0,%1}, [%2];"
                 : "=r"(r[0]), "=r"(r[1]) : "r"(addr));
}
__device__ __forceinline__ void mma16816(float* c, const uint32_t* a, const uint32_t* b) {
    asm volatile("mma.sync.aligned.m16n8k16.row.col.f32.bf16.bf16.f32 "
                 "{%0,%1,%2,%3}, {%4,%5,%6,%7}, {%8,%9}, {%0,%1,%2,%3};"
                 : "+f"(c[0]), "+f"(c[1]), "+f"(c[2]), "+f"(c[3])
                 : "r"(a[0]), "r"(a[1]), "r"(a[2]), "r"(a[3]), "r"(b[0]), "r"(b[1]));
}
__device__ __forceinline__ __nv_bfloat16 bf_hi(float x) { return __float2bfloat16_rn(x); }

// ---------------------------------------------------------------------------
// Preprocessing: bf16 hi/lo splits and transpose-splits
// ---------------------------------------------------------------------------
__global__ void split_x(const float4* __restrict__ src) {
    int i = blockIdx.x * blockDim.x + threadIdx.x;   // MTOT*CB/4 threads
    float4 v = src[i];
    __nv_bfloat162 h01, h23, l01, l23;
    h01.x = bf_hi(v.x); l01.x = bf_hi(v.x - __bfloat162float(h01.x));
    h01.y = bf_hi(v.y); l01.y = bf_hi(v.y - __bfloat162float(h01.y));
    h23.x = bf_hi(v.z); l23.x = bf_hi(v.z - __bfloat162float(h23.x));
    h23.y = bf_hi(v.w); l23.y = bf_hi(v.w - __bfloat162float(h23.y));
    ((__nv_bfloat162*)g_xhi)[2 * i]     = h01;
    ((__nv_bfloat162*)g_xhi)[2 * i + 1] = h23;
    ((__nv_bfloat162*)g_xlo)[2 * i]     = l01;
    ((__nv_bfloat162*)g_xlo)[2 * i + 1] = l23;
}
__global__ void split_y() {
    int i = blockIdx.x * blockDim.x + threadIdx.x;
    float4 v = ((const float4*)g_y)[i];
    __nv_bfloat162 h01, h23, l01, l23;
    h01.x = bf_hi(v.x); l01.x = bf_hi(v.x - __bfloat162float(h01.x));
    h01.y = bf_hi(v.y); l01.y = bf_hi(v.y - __bfloat162float(h01.y));
    h23.x = bf_hi(v.z); l23.x = bf_hi(v.z - __bfloat162float(h23.x));
    h23.y = bf_hi(v.w); l23.y = bf_hi(v.w - __bfloat162float(h23.y));
    ((__nv_bfloat162*)g_yhi)[2 * i]     = h01;
    ((__nv_bfloat162*)g_yhi)[2 * i + 1] = h23;
    ((__nv_bfloat162*)g_ylo)[2 * i]     = l01;
    ((__nv_bfloat162*)g_ylo)[2 * i + 1] = l23;
}
// W [K,N] row-major -> WT_hi/WT_lo [N,K] bf16
template <int SEL>
__global__ void transpose_split(const float* __restrict__ W, int K, int N) {
    __nv_bfloat16* Thi = (SEL == 0) ? g_wqT_hi : g_wpT_hi;
    __nv_bfloat16* Tlo = (SEL == 0) ? g_wqT_lo : g_wpT_lo;
    __shared__ float t[32][33];
    const int n0 = blockIdx.x * 32, k0 = blockIdx.y * 32;
    const int tx = threadIdx.x, ty = threadIdx.y;
    #pragma unroll
    for (int r = ty; r < 32; r += 8)
        t[r][tx] = W[(size_t)(k0 + r) * N + n0 + tx];
    __syncthreads();
    #pragma unroll
    for (int r = ty; r < 32; r += 8) {
        float v = t[tx][r];
        __nv_bfloat16 h = bf_hi(v);
        __nv_bfloat16 l = bf_hi(v - __bfloat162float(h));
        size_t o = (size_t)(n0 + r) * K + k0 + tx;
        Thi[o] = h;
        Tlo[o] = l;
    }
}

// ---------------------------------------------------------------------------
// bf16x3 tensor-core GEMM via mma.sync.m16n8k16. Occupancy-2 variant:
// B fragments cached (16 regs), A fragments loaded per-mt (8 live regs).
// MODE 1 epilogue: q/k/v fp32 + k/v bf16 hi/lo (for HMMA attention).
// ---------------------------------------------------------------------------
#define ST_BYTES  32768                 // per stage: Ahi|Alo|Bhi|Blo, 8KB each
#define TG_SMEM   (3*ST_BYTES)

template <int MODE>
__global__ void __launch_bounds__(256, 2)
tgemm(const float* __restrict__ bias, float* __restrict__ C, int N, int K)
{
    extern __shared__ __align__(128) unsigned char smbuf[];
    const uint32_t sbase = su32(smbuf);
    const int tid = threadIdx.x;
    const int bm = blockIdx.y * 128;
    const int bn = blockIdx.x * 128;

    const __nv_bfloat16* __restrict__ Ahi = (MODE == 1) ? g_xhi : g_yhi;
    const __nv_bfloat16* __restrict__ Alo = (MODE == 1) ? g_xlo : g_ylo;
    const __nv_bfloat16* __restrict__ Bhi = (MODE == 1) ? g_wqT_hi : g_wpT_hi;
    const __nv_bfloat16* __restrict__ Blo = (MODE == 1) ? g_wqT_lo : g_wpT_lo;

    const int NK = K / 32;   // 32

    const int ldrow = tid >> 1;
    const int ldc0  = (tid & 1) * 2;
    auto load_stage = [&](int stage, int k0) {
        const uint32_t sb = sbase + (uint32_t)stage * ST_BYTES;
        #pragma unroll
        for (int cc = 0; cc < 2; cc++) {
            const int c = ldc0 + cc;
            const uint32_t so = (uint32_t)(ldrow * 64 + ((c ^ ((ldrow >> 1) & 3)) << 4));
            const size_t ga = (size_t)(bm + ldrow) * K + k0 + c * 8;
            const size_t gb = (size_t)(bn + ldrow) * K + k0 + c * 8;
            cpa16(sb + so,               Ahi + ga);
            cpa16(sb + 8192 + so,        Alo + ga);
            cpa16(sb + 16384 + so,       Bhi + gb);
            cpa16(sb + 24576 + so,       Blo + gb);
        }
        cpa_commit();
    };

    load_stage(0, 0);
    load_stage(1, 32);

    const int lane = tid & 31, w = tid >> 5;
    const int wm = w >> 2, wn = w & 3;
    const int a_r = lane & 15, a_c = lane >> 4;
    const int b_r = lane & 7,  b_c = (lane >> 3) & 1;

    float acc[4][4][4];
    #pragma unroll
    for (int mt = 0; mt < 4; mt++)
        #pragma unroll
        for (int nt = 0; nt < 4; nt++)
            #pragma unroll
            for (int q = 0; q < 4; q++) acc[mt][nt][q] = 0.f;

    for (int ks = 0; ks < NK; ks++) {
        if (ks == NK - 1) cpa_wait<0>(); else cpa_wait<1>();
        __syncthreads();
        if (ks + 2 < NK) load_stage((ks + 2) % 3, (ks + 2) * 32);

        const uint32_t sb = sbase + (uint32_t)(ks % 3) * ST_BYTES;
        #pragma unroll
        for (int t = 0; t < 2; t++) {
            uint32_t bh[4][2], bl[4][2];
            #pragma unroll
            for (int nt = 0; nt < 4; nt++) {
                const int r = wn * 32 + nt * 8 + b_r;
                const int c = t * 2 + b_c;
                const uint32_t so = (uint32_t)(r * 64 + ((c ^ ((r >> 1) & 3)) << 4));
                ldm_x2(bh[nt], sb + 16384 + so);
                ldm_x2(bl[nt], sb + 24576 + so);
            }
            #pragma unroll
            for (int mt = 0; mt < 4; mt++) {
                uint32_t ah[4], al[4];
                const int r = wm * 64 + mt * 16 + a_r;
                const int c = t * 2 + a_c;
                const uint32_t so = (uint32_t)(r * 64 + ((c ^ ((r >> 1) & 3)) << 4));
                ldm_x4(ah, sb + so);
                ldm_x4(al, sb + 8192 + so);
                #pragma unroll
                for (int nt = 0; nt < 4; nt++) {
                    mma16816(acc[mt][nt], ah, bh[nt]);
                    mma16816(acc[mt][nt], ah, bl[nt]);
                    mma16816(acc[mt][nt], al, bh[nt]);
                }
            }
        }
        __syncthreads();
    }

    const int colq = (lane & 3) * 2;
    const int rowq = lane >> 2;
    #pragma unroll
    for (int nt = 0; nt < 4; nt++) {
        const int cg = bn + wn * 32 + nt * 8 + colq;
        const float b0 = bias[cg], b1 = bias[cg + 1];
        #pragma unroll
        for (int mt = 0; mt < 4; mt++) {
            const int r0 = bm + wm * 64 + mt * 16 + rowq;
            const int r1 = r0 + 8;
            float v00 = acc[mt][nt][0] + b0, v01 = acc[mt][nt][1] + b1;
            float v10 = acc[mt][nt][2] + b0, v11 = acc[mt][nt][3] + b1;
            if (MODE == 0) {
                *(float2*)(C + (size_t)r0 * N + cg) = make_float2(v00, v01);
                *(float2*)(C + (size_t)r1 * N + cg) = make_float2(v10, v11);
            } else {
                const int sec = cg >> 10;            // 0=q,1=k,2=v
                const int f  = cg & 1023;
                const int hh = f >> 6, d0 = f & 63;  // d0 even
                #pragma unroll
                for (int rr = 0; rr < 2; rr++) {
                    const int mrow = rr ? r1 : r0;
                    const float va = rr ? v10 : v00;
                    const float vb = rr ? v11 : v01;
                    const int bidx = mrow >> 12;
                    const int ttk  = mrow & (TT - 1);
                    const int bh2  = bidx * NH + hh;
                    const size_t base = ((size_t)bh2 * TT + ttk) * DH + d0;
                    if (sec == 0) {
                        *(float2*)(g_q + base) = make_float2(va, vb);
                    } else {
                        float* dst = (sec == 1) ? g_k : g_v;
                        *(float2*)(dst + base) = make_float2(va, vb);
                        __nv_bfloat162 h2, l2;
                        h2.x = bf_hi(va); h2.y = bf_hi(vb);
                        l2.x = bf_hi(va - __bfloat162float(h2.x));
                        l2.y = bf_hi(vb - __bfloat162float(h2.y));
                        __nv_bfloat162* dh = (sec == 1) ? (__nv_bfloat162*)g_khi
                                                        : (__nv_bfloat162*)g_vhi;
                        __nv_bfloat162* dl = (sec == 1) ? (__nv_bfloat162*)g_klo
                                                        : (__nv_bfloat162*)g_vlo;
                        dh[base >> 1] = h2;
                        dl[base >> 1] = l2;
                    }
                }
            }
        }
    }
}

// ---------------------------------------------------------------------------
// HMMA flash sparse attention. CTA = 64 queries x (b,h), 8 warps =
// 4 qgroups x 2 kgroups. Window/global blocks use bf16x3 MMA; far-stride
// keys become DIAGONAL blocks (kb = q0-128s, query r <-> key kb+r) processed
// with a cheap SIMT path on fp32 K/V streamed through the same cp.async
// double buffer. No serial tail.
// ---------------------------------------------------------------------------
#define AT_QHI   0
#define AT_QLO   8192
#define AT_KV    16384                 // 2 bufs x 32KB
#define AT_MRG   AT_KV                 // merge buffer reuses KV area (16KB)
#define AT_STAT  (AT_KV + 65536)       // 81920: m[64] l[64] pmax[128] psum[128]
#define ATTN3_SMEM (AT_STAT + 384*4)   // 83456

__global__ void __launch_bounds__(256, 2)
attn3()
{
    extern __shared__ __align__(16) unsigned char smb[];
    const uint32_t sb = su32(smb);
    float* stat = (float*)(smb + AT_STAT);   // [0:64) m, [64:128) l
    float* pmax = stat + 128;                // [2][64] (diag: alpha[64])
    float* psum = stat + 256;                // [2][64] (diag: p[64])

    const int tid  = threadIdx.x;
    const int lane = tid & 31;
    const int w    = tid >> 5;
    const int qg   = w >> 1, kg = w & 1;
    const int rbase = qg * 16;
    const int colbase = kg * 32;
    const int q0 = blockIdx.x * 64;
    const int h  = blockIdx.y;
    const int b  = blockIdx.z;
    const int bh = b * NH + h;

    // ---- load Q fp32 -> bf16 hi/lo smem tiles (chunk-swizzled) ----
    {
        const float* qsrc = g_q + ((size_t)bh * TT + q0) * DH;
        #pragma unroll
        for (int it = 0; it < 2; it++) {
            const int id = tid + it * 256;       // 0..511
            const int row = id >> 3, c = id & 7;
            const float4 f0 = *(const float4*)(qsrc + (size_t)row * DH + c * 8);
            const float4 f1 = *(const float4*)(qsrc + (size_t)row * DH + c * 8 + 4);
            float vv[8] = {f0.x, f0.y, f0.z, f0.w, f1.x, f1.y, f1.z, f1.w};
            __nv_bfloat162 hh[4], ll[4];
            #pragma unroll
            for (int u = 0; u < 4; u++) {
                hh[u].x = bf_hi(vv[2*u]);   hh[u].y = bf_hi(vv[2*u+1]);
                ll[u].x = bf_hi(vv[2*u]   - __bfloat162float(hh[u].x));
                ll[u].y = bf_hi(vv[2*u+1] - __bfloat162float(hh[u].y));
            }
            const uint32_t off = (uint32_t)(row * 128 + ((c ^ (row & 7)) << 4));
            *(uint4*)(smb + AT_QHI + off) = *(uint4*)hh;
            *(uint4*)(smb + AT_QLO + off) = *(uint4*)ll;
        }
        if (tid < 64) { stat[tid] = -INFINITY; stat[64 + tid] = 0.f; }
    }

    // ---- block schedule: [global?] + window blocks + diagonal levels ----
    const int kstart = (q0 > 256) ? (q0 - 256) : 0;
    const int extra  = (kstart > 0) ? 1 : 0;
    const int nwin   = extra + (q0 + 64 - kstart) / 64;
    const int ndiag  = (q0 / 128 >= 3) ? (q0 / 128 - 2) : 0;   // levels s=3..
    const int nb     = nwin + ndiag;
    auto kb_of = [&](int bi) -> int {
        if (extra && bi == 0) return 0;
        if (bi < nwin) return kstart + (bi - extra) * 64;
        return q0 - 128 * (bi - nwin + 3);
    };
    auto is_diag = [&](int bi) -> bool { return bi >= nwin; };

    auto load_kv = [&](int bufn, int kb, bool dg) {
        const uint32_t dst0 = sb + AT_KV + (uint32_t)bufn * 32768;
        if (!dg) {
            const size_t gb = ((size_t)bh * TT + kb) * DH;
            const __nv_bfloat16* srcs[4] = {g_khi + gb, g_klo + gb, g_vhi + gb, g_vlo + gb};
            #pragma unroll
            for (int qq = 0; qq < 8; qq++) {
                const int tile = qq >> 1;
                const int within = tid + (qq & 1) * 256;   // 0..511
                const int row = within >> 3, c = within & 7;
                cpa16(dst0 + tile * 8192 + row * 128 + ((c ^ (row & 7)) << 4),
                      srcs[tile] + (size_t)row * DH + c * 8);
            }
        } else {
            const float* ksrc = g_k + ((size_t)bh * TT + kb) * DH;
            const float* vsrc = g_v + ((size_t)bh * TT + kb) * DH;
            #pragma unroll
            for (int qq = 0; qq < 8; qq++) {
                const int id = tid + qq * 256;       // 0..2047
                const int half = id >> 10;           // 0=K 1=V
                const int r = (id >> 4) & 63;
                const int c = id & 15;
                const int cp = c ^ (r & 15);
                const float* src = half ? vsrc : ksrc;
                cpa16(dst0 + half * 16384 + r * 256 + cp * 16,
                      src + (size_t)r * DH + c * 4);
            }
        }
        cpa_commit();
    };

    load_kv(0, kb_of(0), is_diag(0));

    float o[8][4];
    #pragma unroll
    for (int nt = 0; nt < 8; nt++)
        #pragma unroll
        for (int e = 0; e < 4; e++) o[nt][e] = 0.f;

    const int quad_lo = (lane >> 3) & 1;
    const int quad_hi = lane >> 4;
    const int l7 = lane & 7;
    const int rl = rbase + (lane >> 2);    // fragment low row

    __syncthreads();

    for (int bi = 0; bi < nb; bi++) {
        const int kb  = kb_of(bi);
        const int buf = bi & 1;
        const bool dg = is_diag(bi);
        const bool gonly = (extra && bi == 0);

        if (bi + 1 < nb) { load_kv(buf ^ 1, kb_of(bi + 1), is_diag(bi + 1)); cpa_wait<1>(); }
        else             { cpa_wait<0>(); }
        __syncthreads();

        if (dg) {
            // ======== diagonal block: query row r <-> key kb + r ========
            const float* kd = (const float*)(smb + AT_KV + (uint32_t)buf * 32768);
            const float* vd = kd + 4096;
            const int q = lane & 3;
            const int rowi = w * 8 + (lane >> 2);
            float part = 0.f;
            #pragma unroll
            for (int i4 = 0; i4 < 4; i4++) {
                const int ch = 4 * q + i4;
                const float4 k4 = *(const float4*)(kd + rowi * 64 + ((ch ^ (rowi & 15)) << 2));
                const int d0 = q * 16 + i4 * 4;
                const int c8 = d0 >> 3, sub = d0 & 7;
                const uint32_t qoff = (uint32_t)(rowi * 128 + ((c8 ^ (rowi & 7)) << 4) + sub * 2);
                const __nv_bfloat162 qh0 = *(const __nv_bfloat162*)(smb + AT_QHI + qoff);
                const __nv_bfloat162 qh1 = *(const __nv_bfloat162*)(smb + AT_QHI + qoff + 4);
                const __nv_bfloat162 ql0 = *(const __nv_bfloat162*)(smb + AT_QLO + qoff);
                const __nv_bfloat162 ql1 = *(const __nv_bfloat162*)(smb + AT_QLO + qoff + 4);
                part += (__bfloat162float(qh0.x) + __bfloat162float(ql0.x)) * k4.x;
                part += (__bfloat162float(qh0.y) + __bfloat162float(ql0.y)) * k4.y;
                part += (__bfloat162float(qh1.x) + __bfloat162float(ql1.x)) * k4.z;
                part += (__bfloat162float(qh1.y) + __bfloat162float(ql1.y)) * k4.w;
            }
            part += __shfl_xor_sync(0xffffffffu, part, 1);
            part += __shfl_xor_sync(0xffffffffu, part, 2);
            const int j = kb + rowi;
            const float sv = (j >= NGLOB) ? part * 0.125f : -INFINITY;
            if (q == 0) {
                const float mo = stat[rowi];
                const float mn = fmaxf(mo, sv);
                const float alpha = __expf(mo - mn);        // 1 when sv=-inf
                const float p = __expf(sv - mn);            // 0 when sv=-inf
                stat[rowi] = mn;
                stat[64 + rowi] = stat[64 + rowi] * alpha + p;
                pmax[rowi] = alpha;
                psum[rowi] = p;
            }
            __syncthreads();
            const float al0 = pmax[rl], al1 = pmax[rl + 8];
            #pragma unroll
            for (int nt = 0; nt < 8; nt++) {
                o[nt][0] *= al0; o[nt][1] *= al0;
                o[nt][2] *= al1; o[nt][3] *= al1;
            }
            if (kg == 0) {
                #pragma unroll
                for (int rr = 0; rr < 2; rr++) {
                    const int row = rl + rr * 8;
                    const float p = psum[row];
                    #pragma unroll
                    for (int nt = 0; nt < 8; nt++) {
                        #pragma unroll
                        for (int e = 0; e < 2; e++) {
                            const int col = nt * 8 + 2 * (lane & 3) + e;
                            const float vvv = vd[row * 64 + (((col >> 2) ^ (row & 15)) << 2) + (col & 3)];
                            o[nt][rr * 2 + e] += p * vvv;
                        }
                    }
                }
            }
            __syncthreads();
            continue;
        }

        const uint32_t kvb = sb + AT_KV + (uint32_t)buf * 32768;

        // ---- scores: S[16q x 32k] per warp, bf16x3 ----
        float s[4][4];
        #pragma unroll
        for (int nt = 0; nt < 4; nt++)
            #pragma unroll
            for (int e = 0; e < 4; e++) s[nt][e] = 0.f;

        #pragma unroll
        for (int ks = 0; ks < 4; ks++) {
            uint32_t qh[4], ql[4];
            {
                const int row = rbase + quad_lo * 8 + l7;
                const int ch  = 2 * ks + quad_hi;
                const uint32_t off = (uint32_t)(row * 128 + ((ch ^ (row & 7)) << 4));
                ldm_x4(qh, sb + AT_QHI + off);
                ldm_x4(ql, sb + AT_QLO + off);
            }
            #pragma unroll
            for (int ntp = 0; ntp < 2; ntp++) {
                uint32_t kh[4], kl[4];
                const int rowk = colbase + ntp * 16 + quad_hi * 8 + l7;
                const int chk  = 2 * ks + quad_lo;
                const uint32_t offk = (uint32_t)(rowk * 128 + ((chk ^ (rowk & 7)) << 4));
                ldm_x4(kh, kvb + offk);
                ldm_x4(kl, kvb + 8192 + offk);
                mma16816(s[2*ntp],   qh, kh);
                mma16816(s[2*ntp],   qh, kl);
                mma16816(s[2*ntp],   ql, kh);
                mma16816(s[2*ntp+1], qh, kh + 2);
                mma16816(s[2*ntp+1], qh, kl + 2);
                mma16816(s[2*ntp+1], ql, kh + 2);
            }
        }

        // ---- mask + scale ----
        #pragma unroll
        for (int nt = 0; nt < 4; nt++)
            #pragma unroll
            for (int e = 0; e < 4; e++) {
                const int row = rl + (e >> 1) * 8;
                const int i = q0 + row;
                const int j = kb + colbase + nt * 8 + 2 * (lane & 3) + (e & 1);
                const int dij = i - j;
                const bool ok = gonly ? (j < NGLOB)
                    : (dij >= 0 && (dij < WINDOW || (dij & (STRIDE - 1)) == 0 || j < NGLOB));
                s[nt][e] = ok ? s[nt][e] * 0.125f : -INFINITY;
            }

        // ---- partial row max (warp's 32 cols) ----
        float mx0 = fmaxf(fmaxf(s[0][0], s[0][1]), fmaxf(s[1][0], s[1][1]));
        mx0 = fmaxf(mx0, fmaxf(fmaxf(s[2][0], s[2][1]), fmaxf(s[3][0], s[3][1])));
        float mx1 = fmaxf(fmaxf(s[0][2], s[0][3]), fmaxf(s[1][2], s[1][3]));
        mx1 = fmaxf(mx1, fmaxf(fmaxf(s[2][2], s[2][3]), fmaxf(s[3][2], s[3][3])));
        mx0 = fmaxf(mx0, __shfl_xor_sync(0xffffffffu, mx0, 1));
        mx0 = fmaxf(mx0, __shfl_xor_sync(0xffffffffu, mx0, 2));
        mx1 = fmaxf(mx1, __shfl_xor_sync(0xffffffffu, mx1, 1));
        mx1 = fmaxf(mx1, __shfl_xor_sync(0xffffffffu, mx1, 2));
        if ((lane & 3) == 0) {
            pmax[kg * 64 + rl]     = mx0;
            pmax[kg * 64 + rl + 8] = mx1;
        }
        __syncthreads();

        const float m0 = stat[rl], m1 = stat[rl + 8];
        const float mn0 = fmaxf(m0, fmaxf(pmax[rl],     pmax[64 + rl]));
        const float mn1 = fmaxf(m1, fmaxf(pmax[rl + 8], pmax[64 + rl + 8]));
        const float al0 = __expf(m0 - mn0);
        const float al1 = __expf(m1 - mn1);

        float sum0 = 0.f, sum1 = 0.f;
        #pragma unroll
        for (int nt = 0; nt < 4; nt++) {
            s[nt][0] = __expf(s[nt][0] - mn0); sum0 += s[nt][0];
            s[nt][1] = __expf(s[nt][1] - mn0); sum0 += s[nt][1];
            s[nt][2] = __expf(s[nt][2] - mn1); sum1 += s[nt][2];
            s[nt][3] = __expf(s[nt][3] - mn1); sum1 += s[nt][3];
        }
        sum0 += __shfl_xor_sync(0xffffffffu, sum0, 1);
        sum0 += __shfl_xor_sync(0xffffffffu, sum0, 2);
        sum1 += __shfl_xor_sync(0xffffffffu, sum1, 1);
        sum1 += __shfl_xor_sync(0xffffffffu, sum1, 2);
        if ((lane & 3) == 0) {
            psum[kg * 64 + rl]     = sum0;
            psum[kg * 64 + rl + 8] = sum1;
        }
        __syncthreads();

        if (kg == 0 && (lane & 3) == 0) {
            stat[rl] = mn0; stat[rl + 8] = mn1;
            stat[64 + rl]     = stat[64 + rl]     * al0 + psum[rl]     + psum[64 + rl];
            stat[64 + rl + 8] = stat[64 + rl + 8] * al1 + psum[rl + 8] + psum[64 + rl + 8];
        }

        // ---- rescale O ----
        #pragma unroll
        for (int nt = 0; nt < 8; nt++) {
            o[nt][0] *= al0; o[nt][1] *= al0;
            o[nt][2] *= al1; o[nt][3] *= al1;
        }

        // ---- PV: P (hi/lo) x V (hi/lo), 3 combos ----
        #pragma unroll
        for (int ks2 = 0; ks2 < 2; ks2++) {
            const int t0 = 2 * ks2, t1 = t0 + 1;
            uint32_t pah[4], pal[4];
            {
                __nv_bfloat162 h2, l2;
                #pragma unroll
                for (int u = 0; u < 4; u++) {
                    const int tt = (u < 2) ? t0 : t1;
                    const int e0 = (u & 1) * 2;
                    const float p0 = s[tt][e0], p1 = s[tt][e0 + 1];
                    h2.x = bf_hi(p0); h2.y = bf_hi(p1);
                    l2.x = bf_hi(p0 - __bfloat162float(h2.x));
                    l2.y = bf_hi(p1 - __bfloat162float(h2.y));
                    pah[u] = *(uint32_t*)&h2;
                    pal[u] = *(uint32_t*)&l2;
                }
            }
            const int kb2 = colbase + ks2 * 16;
            #pragma unroll
            for (int ntp = 0; ntp < 4; ntp++) {
                uint32_t vh[4], vl[4];
                const int rowv = kb2 + quad_lo * 8 + l7;
                const int chv  = 2 * ntp + quad_hi;
                const uint32_t offv = (uint32_t)(rowv * 128 + ((chv ^ (rowv & 7)) << 4));
                ldm_x4t(vh, kvb + 16384 + offv);
                ldm_x4t(vl, kvb + 24576 + offv);
                mma16816(o[2*ntp],   pah, vh);
                mma16816(o[2*ntp],   pah, vl);
                mma16816(o[2*ntp],   pal, vh);
                mma16816(o[2*ntp+1], pah, vh + 2);
                mma16816(o[2*ntp+1], pah, vl + 2);
                mma16816(o[2*ntp+1], pal, vh + 2);
            }
        }
        __syncthreads();
    }

    // ---- merge partial O: kg0 keeps rows 0-7, kg1 keeps rows 8-15 ----
    float* mrg = (float*)(smb + AT_MRG);   // [qg][16][64]
    {
        const int wr = (kg == 0) ? (lane >> 2) + 8 : (lane >> 2);
        float* basep = mrg + (qg * 16 + wr) * 64;
        const int c0 = kg ? 0 : 2;
        #pragma unroll
        for (int nt = 0; nt < 8; nt++) {
            basep[nt * 8 + 2 * (lane & 3)]     = o[nt][c0];
            basep[nt * 8 + 2 * (lane & 3) + 1] = o[nt][c0 + 1];
        }
    }
    __syncthreads();
    {
        const int rd = (kg == 0) ? (lane >> 2) : (lane >> 2) + 8;
        const float* basep = mrg + (qg * 16 + rd) * 64;
        const int c0 = kg ? 2 : 0;
        #pragma unroll
        for (int nt = 0; nt < 8; nt++) {
            o[nt][c0]     += basep[nt * 8 + 2 * (lane & 3)];
            o[nt][c0 + 1] += basep[nt * 8 + 2 * (lane & 3) + 1];
        }
    }

    // ---- normalize + write y ----
    {
        const int ce0 = kg ? 2 : 0;
        const int row = rbase + (kg ? 8 : 0) + (lane >> 2);
        const float inv = 1.f / stat[64 + row];
        float* yr = g_y + ((size_t)b * TT + q0 + row) * CB + h * DH;
        #pragma unroll
        for (int nt = 0; nt < 8; nt++)
            *(float2*)(yr + nt * 8 + 2 * (lane & 3)) =
                make_float2(o[nt][ce0] * inv, o[nt][ce0 + 1] * inv);
    }
}

// ---------------------------------------------------------------------------
extern "C" void kernel_launch(void* const* d_in, const int* in_sizes, int n_in,
                              void* d_out, int out_size)
{
    (void)in_sizes; (void)n_in; (void)out_size;
    const float* x      = (const float*)d_in[0];
    const float* w_qkv  = (const float*)d_in[1];
    const float* b_qkv  = (const float*)d_in[2];
    const float* w_proj = (const float*)d_in[3];
    const float* b_proj = (const float*)d_in[4];
    float* out = (float*)d_out;

    cudaFuncSetAttribute(tgemm<1>, cudaFuncAttributeMaxDynamicSharedMemorySize, TG_SMEM);
    cudaFuncSetAttribute(tgemm<0>, cudaFuncAttributeMaxDynamicSharedMemorySize, TG_SMEM);
    cudaFuncSetAttribute(attn3,    cudaFuncAttributeMaxDynamicSharedMemorySize, ATTN3_SMEM);

    // 0) bf16 hi/lo splits of activations + transposed weight splits
    split_x<<<(MTOT * CB / 4) / 256, 256>>>((const float4*)x);
    transpose_split<0><<<dim3(N_QKV / 32, CB / 32), dim3(32, 8)>>>(w_qkv, CB, N_QKV);
    transpose_split<1><<<dim3(CB / 32, CB / 32), dim3(32, 8)>>>(w_proj, CB, CB);

    // 1) QKV GEMM -> q/k/v fp32 + k/v bf16 hi/lo
    tgemm<1><<<dim3(N_QKV / 128, MTOT / 128), 256, TG_SMEM>>>(b_qkv, nullptr, N_QKV, CB);

    // 2) HMMA flash sparse attention (diagonal far-stride blocks) -> g_y
    attn3<<<dim3(TT / 64, NH, BBATCH), 256, ATTN3_SMEM>>>();

    // 3) split y, then output projection GEMM -> d_out
    split_y<<<(MTOT * CB / 4) / 256, 256>>>();
    tgemm<0><<<dim3(CB / 128, MTOT / 128), 256, TG_SMEM>>>(b_proj, out, CB, CB);
}